// round 3
// baseline (speedup 1.0000x reference)
#include <cuda_runtime.h>

#define NV   30000
#define NE   4000
#define DD   256
#define NNZK 960000

// ---------------- scratch (static device globals; 16B+ aligned for v4 ops) ---
__device__ __align__(256) float g_degV[NV];
__device__ __align__(256) float g_colsum[NE];
__device__ __align__(256) float g_degE[NE];
__device__ __align__(256) float g_cnt[NE];
__device__ __align__(256) float g_Xe[NE * DD];          // 4 MB
__device__ __align__(256) float g_Xv[NV * DD];          // 30 MB
__device__ __align__(256) float g_M[DD * DD];           // fused 0.8*W^T + 0.2*I

// vectorized fp32 reduction-add to global (sm_90+)
__device__ __forceinline__ void red_add_v4(float* p, float4 v) {
    asm volatile("red.global.add.v4.f32 [%0], {%1,%2,%3,%4};"
                 :: "l"(p), "f"(v.x), "f"(v.y), "f"(v.z), "f"(v.w)
                 : "memory");
}

// ---------------- zero-init scratch ------------------------------------------
__global__ void k_zero() {
    int i = blockIdx.x * blockDim.x + threadIdx.x;
    int stride = gridDim.x * blockDim.x;
    for (int j = i; j < NE; j += stride) { g_colsum[j] = 0.f; g_cnt[j] = 0.f; }
    for (int j = i; j < NE * DD; j += stride) g_Xe[j] = 0.f;
    for (int j = i; j < NV * DD; j += stride) g_Xv[j] = 0.f;
}

// ---------------- fused H row-sum + col-sum (single 480MB pass) --------------
// grid = 240 blocks, 125 rows each; 256 threads; each thread owns fixed columns
__global__ void __launch_bounds__(256) k_deg(const float* __restrict__ H) {
    __shared__ float s_warp[8];
    const int tid  = threadIdx.x;
    const int lane = tid & 31;
    const int wid  = tid >> 5;

    float cacc[4][4];
    #pragma unroll
    for (int j = 0; j < 4; ++j)
        #pragma unroll
        for (int k = 0; k < 4; ++k) cacc[j][k] = 0.f;

    const int r0 = blockIdx.x * 125;
    const int r1 = (r0 + 125 < NV) ? r0 + 125 : NV;

    for (int r = r0; r < r1; ++r) {
        const float4* row = (const float4*)(H + (size_t)r * NE);
        float part = 0.f;
        #pragma unroll
        for (int j = 0; j < 4; ++j) {
            int c4 = tid + j * 256;                 // float4 index, < 1000
            if (c4 < NE / 4) {
                float4 v = row[c4];
                part += v.x + v.y + v.z + v.w;
                cacc[j][0] += v.x; cacc[j][1] += v.y;
                cacc[j][2] += v.z; cacc[j][3] += v.w;
            }
        }
        #pragma unroll
        for (int o = 16; o > 0; o >>= 1) part += __shfl_xor_sync(~0u, part, o);
        if (lane == 0) s_warp[wid] = part;
        __syncthreads();
        if (tid == 0) {
            float s = 0.f;
            #pragma unroll
            for (int w = 0; w < 8; ++w) s += s_warp[w];
            g_degV[r] = (s > 0.f) ? rsqrtf(s) : 1.0f;  // inf -> 1.0 per ref
        }
        __syncthreads();
    }
    // column partials -> global
    #pragma unroll
    for (int j = 0; j < 4; ++j) {
        int c = 4 * tid + 1024 * j;
        if (c < NE) {
            atomicAdd(&g_colsum[c + 0], cacc[j][0]);
            atomicAdd(&g_colsum[c + 1], cacc[j][1]);
            atomicAdd(&g_colsum[c + 2], cacc[j][2]);
            atomicAdd(&g_colsum[c + 3], cacc[j][3]);
        }
    }
}

__global__ void k_degE() {
    int c = blockIdx.x * blockDim.x + threadIdx.x;
    if (c < NE) g_degE[c] = rsqrtf(g_colsum[c]);   // ref has no inf guard here
}

// ---------------- prep fused GEMM matrix M[k][j] = 0.8*W[j][k] + 0.2*I -------
__global__ void k_prepM(const float* __restrict__ W) {
    int i = blockIdx.x * blockDim.x + threadIdx.x;
    if (i < DD * DD) {
        int k = i >> 8, j = i & 255;
        g_M[i] = 0.8f * W[j * DD + k] + ((k == j) ? 0.2f : 0.f);
    }
}

// ---------------- scatter X rows into edge sums (one warp per nnz) -----------
__global__ void __launch_bounds__(256) k_edge_scatter(
    const float* __restrict__ X,
    const int* __restrict__ vertex,
    const int* __restrict__ edges)
{
    int w = blockIdx.x * 8 + (threadIdx.x >> 5);
    if (w >= NNZK) return;
    int lane = threadIdx.x & 31;
    int v = vertex[w];
    int e = edges[w];
    // defensive clamp: wrong input mapping -> wrong answer (diagnosable), not a crash
    v = (v < 0) ? 0 : (v >= NV ? NV - 1 : v);
    e = (e < 0) ? 0 : (e >= NE ? NE - 1 : e);
    const float4* src = (const float4*)(X + (size_t)v * DD);
    float4* dst       = (float4*)(g_Xe + (size_t)e * DD);
    float4 a = src[lane];
    float4 b = src[lane + 32];
    red_add_v4((float*)(dst + lane), a);
    red_add_v4((float*)(dst + lane + 32), b);
    if (lane == 0) atomicAdd(&g_cnt[e], 1.0f);
}

// ---------------- Xe = (sum/cnt) * degE --------------------------------------
__global__ void k_edge_scale() {
    int i = blockIdx.x * blockDim.x + threadIdx.x;
    if (i < NE * DD) {
        int e = i >> 8;
        float c = fmaxf(g_cnt[e], 1.0f);
        g_Xe[i] = g_Xe[i] * (g_degE[e] / c);
    }
}

// ---------------- scatter edge rows back into vertex sums --------------------
__global__ void __launch_bounds__(256) k_vert_scatter(
    const int* __restrict__ vertex,
    const int* __restrict__ edges)
{
    int w = blockIdx.x * 8 + (threadIdx.x >> 5);
    if (w >= NNZK) return;
    int lane = threadIdx.x & 31;
    int v = vertex[w];
    int e = edges[w];
    v = (v < 0) ? 0 : (v >= NV ? NV - 1 : v);
    e = (e < 0) ? 0 : (e >= NE ? NE - 1 : e);
    const float4* src = (const float4*)(g_Xe + (size_t)e * DD);
    float4* dst       = (float4*)(g_Xv + (size_t)v * DD);
    float4 a = src[lane];
    float4 b = src[lane + 32];
    red_add_v4((float*)(dst + lane), a);
    red_add_v4((float*)(dst + lane + 32), b);
}

// ---------------- fused epilogue GEMM: out = Xi @ M --------------------------
// Xi[n][k] = 0.9*degV[n]*Xv[n][k] + 0.1*X0[n][k] computed at A-tile load.
// 128x128x32 tile, 256 threads, 8x8 per thread.
__global__ void __launch_bounds__(256) k_gemm(const float* __restrict__ X0,
                                              float* __restrict__ out)
{
    __shared__ float As[32][132];   // transposed, padded
    __shared__ float Bs[32][128];

    const int tid  = threadIdx.x;
    const int n0   = blockIdx.x * 128;
    const int j0   = blockIdx.y * 128;
    const int tRow = (tid >> 4) * 8;
    const int tCol = (tid & 15) * 8;

    const int aRow = tid >> 3;          // 0..31
    const int aCol = (tid & 7) * 4;     // 0,4,..28
    const int bCol = (tid & 31) * 4;    // 0..124
    const int bRow = tid >> 5;          // 0..7

    float acc[8][8];
    #pragma unroll
    for (int i = 0; i < 8; ++i)
        #pragma unroll
        for (int j = 0; j < 8; ++j) acc[i][j] = 0.f;

    for (int k0 = 0; k0 < DD; k0 += 32) {
        #pragma unroll
        for (int s = 0; s < 4; ++s) {
            int m = s * 32 + aRow;
            int gRow = n0 + m;
            float4 xv = make_float4(0.f, 0.f, 0.f, 0.f);
            float4 x0 = xv;
            float dv = 0.f;
            if (gRow < NV) {
                size_t off = (size_t)gRow * DD + k0 + aCol;
                xv = *(const float4*)(g_Xv + off);
                x0 = *(const float4*)(X0 + off);
                dv = g_degV[gRow];
            }
            float sc = 0.9f * dv;
            As[aCol + 0][m] = sc * xv.x + 0.1f * x0.x;
            As[aCol + 1][m] = sc * xv.y + 0.1f * x0.y;
            As[aCol + 2][m] = sc * xv.z + 0.1f * x0.z;
            As[aCol + 3][m] = sc * xv.w + 0.1f * x0.w;
        }
        #pragma unroll
        for (int s = 0; s < 4; ++s) {
            int k = s * 8 + bRow;
            float4 b = *(const float4*)(g_M + (size_t)(k0 + k) * DD + j0 + bCol);
            *(float4*)(&Bs[k][bCol]) = b;
        }
        __syncthreads();
        #pragma unroll
        for (int k = 0; k < 32; ++k) {
            float a[8], b[8];
            *(float4*)(a)     = *(const float4*)(&As[k][tRow]);
            *(float4*)(a + 4) = *(const float4*)(&As[k][tRow + 4]);
            *(float4*)(b)     = *(const float4*)(&Bs[k][tCol]);
            *(float4*)(b + 4) = *(const float4*)(&Bs[k][tCol + 4]);
            #pragma unroll
            for (int i = 0; i < 8; ++i)
                #pragma unroll
                for (int j = 0; j < 8; ++j)
                    acc[i][j] += a[i] * b[j];
        }
        __syncthreads();
    }
    #pragma unroll
    for (int i = 0; i < 8; ++i) {
        int n = n0 + tRow + i;
        if (n < NV) {
            float* o = out + (size_t)n * DD + j0 + tCol;
            *(float4*)(o)     = *(float4*)(&acc[i][0]);
            *(float4*)(o + 4) = *(float4*)(&acc[i][4]);
        }
    }
}

// ---------------- launch ------------------------------------------------------
extern "C" void kernel_launch(void* const* d_in, const int* in_sizes, int n_in,
                              void* d_out, int out_size)
{
    const float* X      = (const float*)d_in[0];
    const float* X0     = (const float*)d_in[1];
    const float* H      = (const float*)d_in[2];
    const float* W      = (const float*)d_in[3];
    const int*   vertex = (const int*)d_in[4];
    const int*   edges  = (const int*)d_in[5];
    float* out = (float*)d_out;

    k_zero<<<2048, 256>>>();
    k_deg<<<240, 256>>>(H);
    k_degE<<<(NE + 255) / 256, 256>>>();
    k_prepM<<<(DD * DD + 255) / 256, 256>>>(W);
    k_edge_scatter<<<NNZK / 8, 256>>>(X, vertex, edges);
    k_edge_scale<<<(NE * DD + 255) / 256, 256>>>();
    k_vert_scatter<<<NNZK / 8, 256>>>(vertex, edges);
    k_gemm<<<dim3((NV + 127) / 128, DD / 128), 256>>>(X0, out);
}

// round 5
// speedup vs baseline: 1.2407x; 1.2407x over previous
#include <cuda_runtime.h>

#define NV   30000
#define NE   4000
#define DD   256
#define NNZK 960000

// ---------------- scratch (static device globals; aligned for v4 ops) -------
__device__ __align__(256) float g_degV[NV];
__device__ __align__(256) float g_colsum[NE];
__device__ __align__(256) float g_degE[NE];
__device__ __align__(256) float g_Xe[NE * DD];          // 4 MB
__device__ __align__(256) float g_Xv[NV * DD];          // 30 MB
__device__ __align__(256) float g_M[DD * DD];           // 0.8*W^T + 0.2*I

// CSR scratch
__device__ __align__(256) int g_cnt_e[NE + 1];
__device__ __align__(256) int g_off_e[NE + 1];
__device__ __align__(256) int g_cur_e[NE];
__device__ __align__(256) int g_vlist[NNZK];            // per-edge vertex ids
__device__ __align__(256) int g_cnt_v[NV + 1];
__device__ __align__(256) int g_off_v[NV + 1];
__device__ __align__(256) int g_cur_v[NV];
__device__ __align__(256) int g_elist[NNZK];            // per-vertex edge ids

// ---------------- small zero-init (only histograms/cursors/colsum) ----------
__global__ void k_zero_small() {
    int i = blockIdx.x * blockDim.x + threadIdx.x;
    if (i < NE) { g_colsum[i] = 0.f; g_cnt_e[i] = 0; g_cur_e[i] = 0; }
    if (i < NV) { g_cnt_v[i] = 0; g_cur_v[i] = 0; }
}

// ---------------- fused H row-sum + col-sum (single 480MB pass) --------------
__global__ void __launch_bounds__(256) k_deg(const float* __restrict__ H) {
    __shared__ float s_warp[8];
    const int tid  = threadIdx.x;
    const int lane = tid & 31;
    const int wid  = tid >> 5;

    float cacc[4][4];
    #pragma unroll
    for (int j = 0; j < 4; ++j)
        #pragma unroll
        for (int k = 0; k < 4; ++k) cacc[j][k] = 0.f;

    const int r0 = blockIdx.x * 125;
    const int r1 = (r0 + 125 < NV) ? r0 + 125 : NV;

    for (int r = r0; r < r1; ++r) {
        const float4* row = (const float4*)(H + (size_t)r * NE);
        float part = 0.f;
        #pragma unroll
        for (int j = 0; j < 4; ++j) {
            int c4 = tid + j * 256;
            if (c4 < NE / 4) {
                float4 v = row[c4];
                part += v.x + v.y + v.z + v.w;
                cacc[j][0] += v.x; cacc[j][1] += v.y;
                cacc[j][2] += v.z; cacc[j][3] += v.w;
            }
        }
        #pragma unroll
        for (int o = 16; o > 0; o >>= 1) part += __shfl_xor_sync(~0u, part, o);
        if (lane == 0) s_warp[wid] = part;
        __syncthreads();
        if (tid == 0) {
            float s = 0.f;
            #pragma unroll
            for (int w = 0; w < 8; ++w) s += s_warp[w];
            g_degV[r] = (s > 0.f) ? rsqrtf(s) : 1.0f;
        }
        __syncthreads();
    }
    #pragma unroll
    for (int j = 0; j < 4; ++j) {
        int c = 4 * tid + 1024 * j;
        if (c < NE) {
            atomicAdd(&g_colsum[c + 0], cacc[j][0]);
            atomicAdd(&g_colsum[c + 1], cacc[j][1]);
            atomicAdd(&g_colsum[c + 2], cacc[j][2]);
            atomicAdd(&g_colsum[c + 3], cacc[j][3]);
        }
    }
}

__global__ void k_degE() {
    int c = blockIdx.x * blockDim.x + threadIdx.x;
    if (c < NE) g_degE[c] = rsqrtf(g_colsum[c]);
}

// ---------------- prep fused GEMM matrix M[k][j] = 0.8*W[j][k] + 0.2*I -------
__global__ void k_prepM(const float* __restrict__ W) {
    int i = blockIdx.x * blockDim.x + threadIdx.x;
    if (i < DD * DD) {
        int k = i >> 8, j = i & 255;
        g_M[i] = 0.8f * W[j * DD + k] + ((k == j) ? 0.2f : 0.f);
    }
}

// ---------------- CSR build: histogram --------------------------------------
__global__ void k_hist(const int* __restrict__ vertex, const int* __restrict__ edges) {
    int i = blockIdx.x * blockDim.x + threadIdx.x;
    if (i < NNZK) {
        int v = vertex[i]; v = (v < 0) ? 0 : (v >= NV ? NV - 1 : v);
        int e = edges[i];  e = (e < 0) ? 0 : (e >= NE ? NE - 1 : e);
        atomicAdd(&g_cnt_e[e], 1);
        atomicAdd(&g_cnt_v[v], 1);
    }
}

// single-block exclusive scan (shuffle-based, 1024 threads)
// NOTE: device globals are referenced from DEVICE code only (never passed
// from host — host code cannot take the address of a __device__ symbol).
__device__ __forceinline__ void scan_impl(const int* __restrict__ cnt,
                                          int* __restrict__ off, int n) {
    __shared__ int wsum[32];
    __shared__ int carry_s;
    int lane = threadIdx.x & 31, wid = threadIdx.x >> 5;
    if (threadIdx.x == 0) carry_s = 0;
    __syncthreads();
    for (int base = 0; base < n; base += 1024) {
        int i = base + threadIdx.x;
        int x = (i < n) ? cnt[i] : 0;
        int inc = x;
        #pragma unroll
        for (int d = 1; d < 32; d <<= 1) {
            int t = __shfl_up_sync(~0u, inc, d);
            if (lane >= d) inc += t;
        }
        if (lane == 31) wsum[wid] = inc;
        __syncthreads();
        if (wid == 0) {
            int w = wsum[lane];
            #pragma unroll
            for (int d = 1; d < 32; d <<= 1) {
                int t = __shfl_up_sync(~0u, w, d);
                if (lane >= d) w += t;
            }
            wsum[lane] = w;
        }
        __syncthreads();
        int woff = (wid > 0) ? wsum[wid - 1] : 0;
        if (i < n) off[i] = carry_s + woff + inc - x;
        __syncthreads();
        if (threadIdx.x == 1023) carry_s += wsum[31];
        __syncthreads();
    }
    if (threadIdx.x == 0) off[n] = carry_s;
}

__global__ void __launch_bounds__(1024) k_scan_e() { scan_impl(g_cnt_e, g_off_e, NE); }
__global__ void __launch_bounds__(1024) k_scan_v() { scan_impl(g_cnt_v, g_off_v, NV); }

// fill adjacency lists
__global__ void k_fill(const int* __restrict__ vertex, const int* __restrict__ edges) {
    int i = blockIdx.x * blockDim.x + threadIdx.x;
    if (i < NNZK) {
        int v = vertex[i]; v = (v < 0) ? 0 : (v >= NV ? NV - 1 : v);
        int e = edges[i];  e = (e < 0) ? 0 : (e >= NE ? NE - 1 : e);
        int pe = atomicAdd(&g_cur_e[e], 1);
        g_vlist[g_off_e[e] + pe] = v;
        int pv = atomicAdd(&g_cur_v[v], 1);
        g_elist[g_off_v[v] + pv] = e;
    }
}

// ---------------- edge gather: Xe[e] = degE[e]/cnt * sum_{v in e} X[v] ------
__global__ void __launch_bounds__(256) k_edge_gather(const float* __restrict__ X) {
    const int e   = blockIdx.x;
    const int tid = threadIdx.x;
    const int s = g_off_e[e];
    const int t = g_off_e[e + 1];
    float acc = 0.f;
    int i = s;
    for (; i + 4 <= t; i += 4) {
        int v0 = g_vlist[i], v1 = g_vlist[i + 1], v2 = g_vlist[i + 2], v3 = g_vlist[i + 3];
        float a = X[(size_t)v0 * DD + tid];
        float b = X[(size_t)v1 * DD + tid];
        float c = X[(size_t)v2 * DD + tid];
        float d = X[(size_t)v3 * DD + tid];
        acc += (a + b) + (c + d);
    }
    for (; i < t; ++i) acc += X[(size_t)g_vlist[i] * DD + tid];
    float cnt = (float)(t - s);
    cnt = fmaxf(cnt, 1.0f);
    g_Xe[(size_t)e * DD + tid] = acc * (g_degE[e] / cnt);
}

// ---------------- vertex gather: Xv[v] = sum_{e ∋ v} Xe[e] ------------------
__global__ void __launch_bounds__(256) k_vert_gather() {
    int v = blockIdx.x * 8 + (threadIdx.x >> 5);
    if (v >= NV) return;
    const int lane = threadIdx.x & 31;
    const int s = g_off_v[v];
    const int t = g_off_v[v + 1];
    float4 a0 = make_float4(0.f, 0.f, 0.f, 0.f);
    float4 a1 = a0;
    int i = s;
    for (; i + 2 <= t; i += 2) {
        int e0 = g_elist[i], e1 = g_elist[i + 1];
        const float4* r0 = (const float4*)(g_Xe + (size_t)e0 * DD);
        const float4* r1 = (const float4*)(g_Xe + (size_t)e1 * DD);
        float4 x0 = r0[lane], y0 = r0[lane + 32];
        float4 x1 = r1[lane], y1 = r1[lane + 32];
        a0.x += x0.x + x1.x; a0.y += x0.y + x1.y; a0.z += x0.z + x1.z; a0.w += x0.w + x1.w;
        a1.x += y0.x + y1.x; a1.y += y0.y + y1.y; a1.z += y0.z + y1.z; a1.w += y0.w + y1.w;
    }
    if (i < t) {
        int e0 = g_elist[i];
        const float4* r0 = (const float4*)(g_Xe + (size_t)e0 * DD);
        float4 x0 = r0[lane], y0 = r0[lane + 32];
        a0.x += x0.x; a0.y += x0.y; a0.z += x0.z; a0.w += x0.w;
        a1.x += y0.x; a1.y += y0.y; a1.z += y0.z; a1.w += y0.w;
    }
    float4* dst = (float4*)(g_Xv + (size_t)v * DD);
    dst[lane]      = a0;
    dst[lane + 32] = a1;
}

// ---------------- fused epilogue GEMM: out = Xi @ M --------------------------
__global__ void __launch_bounds__(256) k_gemm(const float* __restrict__ X0,
                                              float* __restrict__ out)
{
    __shared__ float As[32][132];
    __shared__ float Bs[32][128];

    const int tid  = threadIdx.x;
    const int n0   = blockIdx.x * 128;
    const int j0   = blockIdx.y * 128;
    const int tRow = (tid >> 4) * 8;
    const int tCol = (tid & 15) * 8;

    const int aRow = tid >> 3;
    const int aCol = (tid & 7) * 4;
    const int bCol = (tid & 31) * 4;
    const int bRow = tid >> 5;

    float acc[8][8];
    #pragma unroll
    for (int i = 0; i < 8; ++i)
        #pragma unroll
        for (int j = 0; j < 8; ++j) acc[i][j] = 0.f;

    for (int k0 = 0; k0 < DD; k0 += 32) {
        #pragma unroll
        for (int s = 0; s < 4; ++s) {
            int m = s * 32 + aRow;
            int gRow = n0 + m;
            float4 xv = make_float4(0.f, 0.f, 0.f, 0.f);
            float4 x0 = xv;
            float dv = 0.f;
            if (gRow < NV) {
                size_t off = (size_t)gRow * DD + k0 + aCol;
                xv = *(const float4*)(g_Xv + off);
                x0 = *(const float4*)(X0 + off);
                dv = g_degV[gRow];
            }
            float sc = 0.9f * dv;
            As[aCol + 0][m] = sc * xv.x + 0.1f * x0.x;
            As[aCol + 1][m] = sc * xv.y + 0.1f * x0.y;
            As[aCol + 2][m] = sc * xv.z + 0.1f * x0.z;
            As[aCol + 3][m] = sc * xv.w + 0.1f * x0.w;
        }
        #pragma unroll
        for (int s = 0; s < 4; ++s) {
            int k = s * 8 + bRow;
            float4 b = *(const float4*)(g_M + (size_t)(k0 + k) * DD + j0 + bCol);
            *(float4*)(&Bs[k][bCol]) = b;
        }
        __syncthreads();
        #pragma unroll
        for (int k = 0; k < 32; ++k) {
            float a[8], b[8];
            *(float4*)(a)     = *(const float4*)(&As[k][tRow]);
            *(float4*)(a + 4) = *(const float4*)(&As[k][tRow + 4]);
            *(float4*)(b)     = *(const float4*)(&Bs[k][tCol]);
            *(float4*)(b + 4) = *(const float4*)(&Bs[k][tCol + 4]);
            #pragma unroll
            for (int i = 0; i < 8; ++i)
                #pragma unroll
                for (int j = 0; j < 8; ++j)
                    acc[i][j] += a[i] * b[j];
        }
        __syncthreads();
    }
    #pragma unroll
    for (int i = 0; i < 8; ++i) {
        int n = n0 + tRow + i;
        if (n < NV) {
            float* o = out + (size_t)n * DD + j0 + tCol;
            *(float4*)(o)     = *(float4*)(&acc[i][0]);
            *(float4*)(o + 4) = *(float4*)(&acc[i][4]);
        }
    }
}

// ---------------- launch ------------------------------------------------------
extern "C" void kernel_launch(void* const* d_in, const int* in_sizes, int n_in,
                              void* d_out, int out_size)
{
    const float* X      = (const float*)d_in[0];
    const float* X0     = (const float*)d_in[1];
    const float* H      = (const float*)d_in[2];
    const float* W      = (const float*)d_in[3];
    const int*   vertex = (const int*)d_in[4];
    const int*   edges  = (const int*)d_in[5];
    float* out = (float*)d_out;

    k_zero_small<<<(NV + 255) / 256, 256>>>();
    k_deg<<<240, 256>>>(H);
    k_degE<<<(NE + 255) / 256, 256>>>();
    k_prepM<<<(DD * DD + 255) / 256, 256>>>(W);
    k_hist<<<(NNZK + 255) / 256, 256>>>(vertex, edges);
    k_scan_e<<<1, 1024>>>();
    k_scan_v<<<1, 1024>>>();
    k_fill<<<(NNZK + 255) / 256, 256>>>(vertex, edges);
    k_edge_gather<<<NE, 256>>>(X);
    k_vert_gather<<<(NV + 7) / 8, 256>>>();
    k_gemm<<<dim3((NV + 127) / 128, DD / 128), 256>>>(X0, out);
}

// round 6
// speedup vs baseline: 1.2653x; 1.0198x over previous
#include <cuda_runtime.h>
#include <cstdint>

#define NV   30000
#define NE   4000
#define DD   256
#define NNZK 960000

// ---------------- scratch (static device globals; aligned) ------------------
__device__ __align__(256) float g_degV[NV];
__device__ __align__(256) float g_colsum[NE];
__device__ __align__(256) float g_Xe[NE * DD];            // 4 MB
__device__ __align__(256) float g_Xv[NV * DD];            // 30 MB
__device__ __align__(256) unsigned g_Mh[DD * DD];         // tf32 hi of 0.8*W^T+0.2I (as [j][k])
__device__ __align__(256) unsigned g_Ml[DD * DD];         // tf32 lo

// CSR scratch
__device__ __align__(256) int g_cnt_e[NE + 1];
__device__ __align__(256) int g_off_e[NE + 1];
__device__ __align__(256) int g_cur_e[NE];
__device__ __align__(256) int g_vlist[NNZK];
__device__ __align__(256) int g_cnt_v[NV + 1];
__device__ __align__(256) int g_off_v[NV + 1];
__device__ __align__(256) int g_cur_v[NV];
__device__ __align__(256) int g_elist[NNZK];

// ---------------- tf32 helpers ----------------------------------------------
__device__ __forceinline__ unsigned f2tf32(float x) {
    unsigned r; asm("cvt.rna.tf32.f32 %0, %1;" : "=r"(r) : "f"(x)); return r;
}
__device__ __forceinline__ void mma_tf32(float* d, const unsigned* a, const unsigned* b) {
    asm volatile(
        "mma.sync.aligned.m16n8k8.row.col.f32.tf32.tf32.f32 "
        "{%0,%1,%2,%3}, {%4,%5,%6,%7}, {%8,%9}, {%0,%1,%2,%3};\n"
        : "+f"(d[0]), "+f"(d[1]), "+f"(d[2]), "+f"(d[3])
        : "r"(a[0]), "r"(a[1]), "r"(a[2]), "r"(a[3]), "r"(b[0]), "r"(b[1]));
}

// ---------------- small zero-init -------------------------------------------
__global__ void k_zero_small() {
    int i = blockIdx.x * blockDim.x + threadIdx.x;
    if (i < NE) { g_colsum[i] = 0.f; g_cnt_e[i] = 0; g_cur_e[i] = 0; }
    if (i < NV) { g_cnt_v[i] = 0; g_cur_v[i] = 0; }
}

// ---------------- CSR build: histogram --------------------------------------
__global__ void k_hist(const int* __restrict__ vertex, const int* __restrict__ edges) {
    int i = blockIdx.x * blockDim.x + threadIdx.x;
    if (i < NNZK) {
        int v = vertex[i]; v = (v < 0) ? 0 : (v >= NV ? NV - 1 : v);
        int e = edges[i];  e = (e < 0) ? 0 : (e >= NE ? NE - 1 : e);
        atomicAdd(&g_cnt_e[e], 1);
        atomicAdd(&g_cnt_v[v], 1);
    }
}

// single-block exclusive scan (device-side symbol refs only)
__device__ __forceinline__ void scan_impl(const int* __restrict__ cnt,
                                          int* __restrict__ off, int n) {
    __shared__ int wsum[32];
    __shared__ int carry_s;
    int lane = threadIdx.x & 31, wid = threadIdx.x >> 5;
    if (threadIdx.x == 0) carry_s = 0;
    __syncthreads();
    for (int base = 0; base < n; base += 1024) {
        int i = base + threadIdx.x;
        int x = (i < n) ? cnt[i] : 0;
        int inc = x;
        #pragma unroll
        for (int d = 1; d < 32; d <<= 1) {
            int t = __shfl_up_sync(~0u, inc, d);
            if (lane >= d) inc += t;
        }
        if (lane == 31) wsum[wid] = inc;
        __syncthreads();
        if (wid == 0) {
            int w = wsum[lane];
            #pragma unroll
            for (int d = 1; d < 32; d <<= 1) {
                int t = __shfl_up_sync(~0u, w, d);
                if (lane >= d) w += t;
            }
            wsum[lane] = w;
        }
        __syncthreads();
        int woff = (wid > 0) ? wsum[wid - 1] : 0;
        if (i < n) off[i] = carry_s + woff + inc - x;
        __syncthreads();
        if (threadIdx.x == 1023) carry_s += wsum[31];
        __syncthreads();
    }
    if (threadIdx.x == 0) off[n] = carry_s;
}
__global__ void __launch_bounds__(1024) k_scan_e() { scan_impl(g_cnt_e, g_off_e, NE); }
__global__ void __launch_bounds__(1024) k_scan_v() { scan_impl(g_cnt_v, g_off_v, NV); }

// ---------------- fused H row-sum + col-sum (single 480MB pass) --------------
__global__ void __launch_bounds__(256) k_deg(const float* __restrict__ H) {
    __shared__ float s_warp[8];
    const int tid  = threadIdx.x;
    const int lane = tid & 31;
    const int wid  = tid >> 5;

    float cacc[4][4];
    #pragma unroll
    for (int j = 0; j < 4; ++j)
        #pragma unroll
        for (int k = 0; k < 4; ++k) cacc[j][k] = 0.f;

    const int r0 = blockIdx.x * 125;
    const int r1 = (r0 + 125 < NV) ? r0 + 125 : NV;

    for (int r = r0; r < r1; ++r) {
        const float4* row = (const float4*)(H + (size_t)r * NE);
        float part = 0.f;
        #pragma unroll
        for (int j = 0; j < 4; ++j) {
            int c4 = tid + j * 256;
            if (c4 < NE / 4) {
                float4 v = row[c4];
                part += v.x + v.y + v.z + v.w;
                cacc[j][0] += v.x; cacc[j][1] += v.y;
                cacc[j][2] += v.z; cacc[j][3] += v.w;
            }
        }
        #pragma unroll
        for (int o = 16; o > 0; o >>= 1) part += __shfl_xor_sync(~0u, part, o);
        if (lane == 0) s_warp[wid] = part;
        __syncthreads();
        if (tid == 0) {
            float s = 0.f;
            #pragma unroll
            for (int w = 0; w < 8; ++w) s += s_warp[w];
            g_degV[r] = (s > 0.f) ? rsqrtf(s) : 1.0f;
        }
        __syncthreads();
    }
    #pragma unroll
    for (int j = 0; j < 4; ++j) {
        int c = 4 * tid + 1024 * j;
        if (c < NE) {
            atomicAdd(&g_colsum[c + 0], cacc[j][0]);
            atomicAdd(&g_colsum[c + 1], cacc[j][1]);
            atomicAdd(&g_colsum[c + 2], cacc[j][2]);
            atomicAdd(&g_colsum[c + 3], cacc[j][3]);
        }
    }
}

// fill adjacency lists
__global__ void k_fill(const int* __restrict__ vertex, const int* __restrict__ edges) {
    int i = blockIdx.x * blockDim.x + threadIdx.x;
    if (i < NNZK) {
        int v = vertex[i]; v = (v < 0) ? 0 : (v >= NV ? NV - 1 : v);
        int e = edges[i];  e = (e < 0) ? 0 : (e >= NE ? NE - 1 : e);
        int pe = atomicAdd(&g_cur_e[e], 1);
        g_vlist[g_off_e[e] + pe] = v;
        int pv = atomicAdd(&g_cur_v[v], 1);
        g_elist[g_off_v[v] + pv] = e;
    }
}

// ---------------- prep tf32-split GEMM matrix Mt[j][k] = 0.8*W[j][k]+0.2*I --
__global__ void k_prepM(const float* __restrict__ W) {
    int i = blockIdx.x * blockDim.x + threadIdx.x;
    if (i < DD * DD) {
        int j = i >> 8, k = i & 255;
        float m = 0.8f * W[i] + ((j == k) ? 0.2f : 0.f);
        unsigned hi = f2tf32(m);
        g_Mh[i] = hi;
        g_Ml[i] = f2tf32(m - __uint_as_float(hi));
    }
}

// ---------------- edge gather: Xe[e] = rsqrt(colsum)/cnt * sum X[v] ---------
__global__ void __launch_bounds__(256) k_edge_gather(const float* __restrict__ X) {
    const int e   = blockIdx.x;
    const int tid = threadIdx.x;
    const int s = g_off_e[e];
    const int t = g_off_e[e + 1];
    float acc = 0.f;
    int i = s;
    for (; i + 8 <= t; i += 8) {
        int v0 = g_vlist[i],     v1 = g_vlist[i + 1], v2 = g_vlist[i + 2], v3 = g_vlist[i + 3];
        int v4 = g_vlist[i + 4], v5 = g_vlist[i + 5], v6 = g_vlist[i + 6], v7 = g_vlist[i + 7];
        float a = X[(size_t)v0 * DD + tid];
        float b = X[(size_t)v1 * DD + tid];
        float c = X[(size_t)v2 * DD + tid];
        float d = X[(size_t)v3 * DD + tid];
        float a2 = X[(size_t)v4 * DD + tid];
        float b2 = X[(size_t)v5 * DD + tid];
        float c2 = X[(size_t)v6 * DD + tid];
        float d2 = X[(size_t)v7 * DD + tid];
        acc += ((a + b) + (c + d)) + ((a2 + b2) + (c2 + d2));
    }
    for (; i < t; ++i) acc += X[(size_t)g_vlist[i] * DD + tid];
    float cnt = fmaxf((float)(t - s), 1.0f);
    float scale = rsqrtf(g_colsum[e]) / cnt;          // degE folded in
    g_Xe[(size_t)e * DD + tid] = acc * scale;
}

// ---------------- vertex gather: Xv[v] = sum_{e ∋ v} Xe[e] ------------------
__global__ void __launch_bounds__(256) k_vert_gather() {
    int v = blockIdx.x * 8 + (threadIdx.x >> 5);
    if (v >= NV) return;
    const int lane = threadIdx.x & 31;
    const int s = g_off_v[v];
    const int t = g_off_v[v + 1];
    float4 a0 = make_float4(0.f, 0.f, 0.f, 0.f);
    float4 a1 = a0;
    int i = s;
    for (; i + 4 <= t; i += 4) {
        int e0 = g_elist[i], e1 = g_elist[i + 1], e2 = g_elist[i + 2], e3 = g_elist[i + 3];
        const float4* r0 = (const float4*)(g_Xe + (size_t)e0 * DD);
        const float4* r1 = (const float4*)(g_Xe + (size_t)e1 * DD);
        const float4* r2 = (const float4*)(g_Xe + (size_t)e2 * DD);
        const float4* r3 = (const float4*)(g_Xe + (size_t)e3 * DD);
        float4 x0 = r0[lane], y0 = r0[lane + 32];
        float4 x1 = r1[lane], y1 = r1[lane + 32];
        float4 x2 = r2[lane], y2 = r2[lane + 32];
        float4 x3 = r3[lane], y3 = r3[lane + 32];
        a0.x += (x0.x + x1.x) + (x2.x + x3.x); a0.y += (x0.y + x1.y) + (x2.y + x3.y);
        a0.z += (x0.z + x1.z) + (x2.z + x3.z); a0.w += (x0.w + x1.w) + (x2.w + x3.w);
        a1.x += (y0.x + y1.x) + (y2.x + y3.x); a1.y += (y0.y + y1.y) + (y2.y + y3.y);
        a1.z += (y0.z + y1.z) + (y2.z + y3.z); a1.w += (y0.w + y1.w) + (y2.w + y3.w);
    }
    for (; i < t; ++i) {
        const float4* r0 = (const float4*)(g_Xe + (size_t)g_elist[i] * DD);
        float4 x0 = r0[lane], y0 = r0[lane + 32];
        a0.x += x0.x; a0.y += x0.y; a0.z += x0.z; a0.w += x0.w;
        a1.x += y0.x; a1.y += y0.y; a1.z += y0.z; a1.w += y0.w;
    }
    float4* dst = (float4*)(g_Xv + (size_t)v * DD);
    dst[lane]      = a0;
    dst[lane + 32] = a1;
}

// ---------------- 3xTF32 tensor-core GEMM: out = Xi @ M ---------------------
// Xi[n][k] = 0.9*degV[n]*Xv[n][k] + 0.1*X0[n][k], computed at A-tile load.
// Block 128x128, K-tile 16. 8 warps: warp = 32(m) x 64(n).
__global__ void __launch_bounds__(256) k_gemm(const float* __restrict__ X0,
                                              float* __restrict__ out)
{
    __shared__ unsigned As_hi[16][132];
    __shared__ unsigned As_lo[16][132];
    __shared__ unsigned Bs_hi[128][20];
    __shared__ unsigned Bs_lo[128][20];

    const int tid  = threadIdx.x;
    const int lane = tid & 31;
    const int wid  = tid >> 5;
    const int gid  = lane >> 2;        // 0..7
    const int tig  = lane & 3;         // 0..3
    const int wr   = wid & 3;          // m-slice: wr*32
    const int wc   = wid >> 2;         // n-slice: wc*64
    const int n0   = blockIdx.x * 128;
    const int j0   = blockIdx.y * 128;

    const int lrow  = tid >> 1;        // 0..127
    const int lhalf = (tid & 1) * 8;   // k offset 0 or 8

    float acc[2][8][4];
    #pragma unroll
    for (int mb = 0; mb < 2; ++mb)
        #pragma unroll
        for (int nb = 0; nb < 8; ++nb)
            #pragma unroll
            for (int c = 0; c < 4; ++c) acc[mb][nb][c] = 0.f;

    const int gRow = n0 + lrow;
    const float dv = (gRow < NV) ? g_degV[gRow] : 0.f;
    const float sc = 0.9f * dv;

    for (int k0 = 0; k0 < DD; k0 += 16) {
        // ---- A producer: 8 Xi values per thread -> split hi/lo, transpose ----
        float xi[8];
        if (gRow < NV) {
            size_t off = (size_t)gRow * DD + k0 + lhalf;
            float4 xa = *(const float4*)(g_Xv + off);
            float4 xb = *(const float4*)(g_Xv + off + 4);
            float4 za = *(const float4*)(X0 + off);
            float4 zb = *(const float4*)(X0 + off + 4);
            xi[0] = sc * xa.x + 0.1f * za.x; xi[1] = sc * xa.y + 0.1f * za.y;
            xi[2] = sc * xa.z + 0.1f * za.z; xi[3] = sc * xa.w + 0.1f * za.w;
            xi[4] = sc * xb.x + 0.1f * zb.x; xi[5] = sc * xb.y + 0.1f * zb.y;
            xi[6] = sc * xb.z + 0.1f * zb.z; xi[7] = sc * xb.w + 0.1f * zb.w;
        } else {
            #pragma unroll
            for (int c = 0; c < 8; ++c) xi[c] = 0.f;
        }
        #pragma unroll
        for (int c = 0; c < 8; ++c) {
            unsigned hi = f2tf32(xi[c]);
            As_hi[lhalf + c][lrow] = hi;
            As_lo[lhalf + c][lrow] = f2tf32(xi[c] - __uint_as_float(hi));
        }
        // ---- B producer: 8 Mt values per thread (pre-split in global) --------
        {
            size_t off = (size_t)(j0 + lrow) * DD + k0 + lhalf;
            uint4 h0 = *(const uint4*)(g_Mh + off);
            uint4 h1 = *(const uint4*)(g_Mh + off + 4);
            uint4 l0 = *(const uint4*)(g_Ml + off);
            uint4 l1 = *(const uint4*)(g_Ml + off + 4);
            *(uint4*)&Bs_hi[lrow][lhalf]     = h0;
            *(uint4*)&Bs_hi[lrow][lhalf + 4] = h1;
            *(uint4*)&Bs_lo[lrow][lhalf]     = l0;
            *(uint4*)&Bs_lo[lrow][lhalf + 4] = l1;
        }
        __syncthreads();

        #pragma unroll
        for (int kk = 0; kk < 16; kk += 8) {
            unsigned bh[8][2], bl[8][2];
            #pragma unroll
            for (int nb = 0; nb < 8; ++nb) {
                int n = wc * 64 + nb * 8 + gid;
                bh[nb][0] = Bs_hi[n][kk + tig];
                bh[nb][1] = Bs_hi[n][kk + tig + 4];
                bl[nb][0] = Bs_lo[n][kk + tig];
                bl[nb][1] = Bs_lo[n][kk + tig + 4];
            }
            #pragma unroll
            for (int mb = 0; mb < 2; ++mb) {
                int m = wr * 32 + mb * 16 + gid;
                unsigned ah[4], al[4];
                ah[0] = As_hi[kk + tig][m];     ah[1] = As_hi[kk + tig][m + 8];
                ah[2] = As_hi[kk + tig + 4][m]; ah[3] = As_hi[kk + tig + 4][m + 8];
                al[0] = As_lo[kk + tig][m];     al[1] = As_lo[kk + tig][m + 8];
                al[2] = As_lo[kk + tig + 4][m]; al[3] = As_lo[kk + tig + 4][m + 8];
                #pragma unroll
                for (int nb = 0; nb < 8; ++nb) {
                    mma_tf32(acc[mb][nb], ah, bh[nb]);
                    mma_tf32(acc[mb][nb], ah, bl[nb]);
                    mma_tf32(acc[mb][nb], al, bh[nb]);
                }
            }
        }
        __syncthreads();
    }

    // ---- epilogue ----
    #pragma unroll
    for (int mb = 0; mb < 2; ++mb) {
        int row = n0 + wr * 32 + mb * 16 + gid;
        #pragma unroll
        for (int nb = 0; nb < 8; ++nb) {
            int col = j0 + wc * 64 + nb * 8 + tig * 2;
            if (row < NV) {
                float2 v = make_float2(acc[mb][nb][0], acc[mb][nb][1]);
                *(float2*)(out + (size_t)row * DD + col) = v;
            }
            if (row + 8 < NV) {
                float2 v = make_float2(acc[mb][nb][2], acc[mb][nb][3]);
                *(float2*)(out + (size_t)(row + 8) * DD + col) = v;
            }
        }
    }
}

// ---------------- launch ------------------------------------------------------
extern "C" void kernel_launch(void* const* d_in, const int* in_sizes, int n_in,
                              void* d_out, int out_size)
{
    const float* X      = (const float*)d_in[0];
    const float* X0     = (const float*)d_in[1];
    const float* H      = (const float*)d_in[2];
    const float* W      = (const float*)d_in[3];
    const int*   vertex = (const int*)d_in[4];
    const int*   edges  = (const int*)d_in[5];
    float* out = (float*)d_out;

    k_zero_small<<<(NV + 255) / 256, 256>>>();                 // 1
    k_hist<<<(NNZK + 255) / 256, 256>>>(vertex, edges);        // 2
    k_scan_e<<<1, 1024>>>();                                   // 3
    k_deg<<<240, 256>>>(H);                                    // 4  <- profiled slot
    k_scan_v<<<1, 1024>>>();                                   // 5
    k_fill<<<(NNZK + 255) / 256, 256>>>(vertex, edges);        // 6
    k_prepM<<<(DD * DD + 255) / 256, 256>>>(W);                // 7
    k_edge_gather<<<NE, 256>>>(X);                             // 8
    k_vert_gather<<<(NV + 7) / 8, 256>>>();                    // 9
    k_gemm<<<dim3((NV + 127) / 128, DD / 128), 256>>>(X0, out);// 10
}

// round 7
// speedup vs baseline: 1.2957x; 1.0240x over previous
#include <cuda_runtime.h>
#include <cstdint>

#define NV   30000
#define NE   4000
#define DD   256
#define NNZK 960000

// ---------------- scratch (static device globals; aligned) ------------------
__device__ __align__(256) float g_degV[NV];
__device__ __align__(256) float g_colsum[NE];
__device__ __align__(256) float g_Xe[NE * DD];            // 4 MB
__device__ __align__(256) float g_Xv[NV * DD];            // 30 MB
__device__ __align__(256) unsigned g_Mh[DD * DD];         // tf32 hi of 0.8*W^T+0.2I (as [j][k])
__device__ __align__(256) unsigned g_Ml[DD * DD];         // tf32 lo

// CSR scratch
__device__ __align__(256) int g_cnt_e[NE + 1];
__device__ __align__(256) int g_off_e[NE + 1];
__device__ __align__(256) int g_cur_e[NE];
__device__ __align__(256) int g_vlist[NNZK];
__device__ __align__(256) int g_cnt_v[NV + 1];
__device__ __align__(256) int g_off_v[NV + 1];
__device__ __align__(256) int g_cur_v[NV];
__device__ __align__(256) int g_elist[NNZK];

// ---------------- tf32 helpers ----------------------------------------------
__device__ __forceinline__ unsigned f2tf32(float x) {
    unsigned r; asm("cvt.rna.tf32.f32 %0, %1;" : "=r"(r) : "f"(x)); return r;
}
__device__ __forceinline__ void mma_tf32(float* d, const unsigned* a, const unsigned* b) {
    asm volatile(
        "mma.sync.aligned.m16n8k8.row.col.f32.tf32.tf32.f32 "
        "{%0,%1,%2,%3}, {%4,%5,%6,%7}, {%8,%9}, {%0,%1,%2,%3};\n"
        : "+f"(d[0]), "+f"(d[1]), "+f"(d[2]), "+f"(d[3])
        : "r"(a[0]), "r"(a[1]), "r"(a[2]), "r"(a[3]), "r"(b[0]), "r"(b[1]));
}

// ---------------- small zero-init -------------------------------------------
__global__ void k_zero_small() {
    int i = blockIdx.x * blockDim.x + threadIdx.x;
    if (i < NE) { g_colsum[i] = 0.f; g_cnt_e[i] = 0; g_cur_e[i] = 0; }
    if (i < NV) { g_cnt_v[i] = 0; g_cur_v[i] = 0; }
}

// ---------------- CSR build: histogram --------------------------------------
__global__ void k_hist(const int* __restrict__ vertex, const int* __restrict__ edges) {
    int i = blockIdx.x * blockDim.x + threadIdx.x;
    if (i < NNZK) {
        int v = vertex[i]; v = (v < 0) ? 0 : (v >= NV ? NV - 1 : v);
        int e = edges[i];  e = (e < 0) ? 0 : (e >= NE ? NE - 1 : e);
        atomicAdd(&g_cnt_e[e], 1);
        atomicAdd(&g_cnt_v[v], 1);
    }
}

// single-block exclusive scan (device-side symbol refs only)
__device__ __forceinline__ void scan_impl(const int* __restrict__ cnt,
                                          int* __restrict__ off, int n) {
    __shared__ int wsum[32];
    __shared__ int carry_s;
    int lane = threadIdx.x & 31, wid = threadIdx.x >> 5;
    if (threadIdx.x == 0) carry_s = 0;
    __syncthreads();
    for (int base = 0; base < n; base += 1024) {
        int i = base + threadIdx.x;
        int x = (i < n) ? cnt[i] : 0;
        int inc = x;
        #pragma unroll
        for (int d = 1; d < 32; d <<= 1) {
            int t = __shfl_up_sync(~0u, inc, d);
            if (lane >= d) inc += t;
        }
        if (lane == 31) wsum[wid] = inc;
        __syncthreads();
        if (wid == 0) {
            int w = wsum[lane];
            #pragma unroll
            for (int d = 1; d < 32; d <<= 1) {
                int t = __shfl_up_sync(~0u, w, d);
                if (lane >= d) w += t;
            }
            wsum[lane] = w;
        }
        __syncthreads();
        int woff = (wid > 0) ? wsum[wid - 1] : 0;
        if (i < n) off[i] = carry_s + woff + inc - x;
        __syncthreads();
        if (threadIdx.x == 1023) carry_s += wsum[31];
        __syncthreads();
    }
    if (threadIdx.x == 0) off[n] = carry_s;
}
__global__ void __launch_bounds__(1024) k_scan_e() { scan_impl(g_cnt_e, g_off_e, NE); }
__global__ void __launch_bounds__(1024) k_scan_v() { scan_impl(g_cnt_v, g_off_v, NV); }

// ---------------- fused H row-sum + col-sum (single 480MB pass) --------------
// 938 blocks x 32 rows. NO per-row block barrier: warp shuffle-reduce + one
// shared atomicAdd per warp per row. Column partials live in registers.
#define DEG_ROWS 32
__global__ void __launch_bounds__(256) k_deg(const float* __restrict__ H) {
    __shared__ float s_row[DEG_ROWS];
    const int tid  = threadIdx.x;
    const int lane = tid & 31;

    if (tid < DEG_ROWS) s_row[tid] = 0.f;
    __syncthreads();

    float cacc[4][4];
    #pragma unroll
    for (int j = 0; j < 4; ++j)
        #pragma unroll
        for (int k = 0; k < 4; ++k) cacc[j][k] = 0.f;

    const int r0 = blockIdx.x * DEG_ROWS;
    const int r1 = (r0 + DEG_ROWS < NV) ? r0 + DEG_ROWS : NV;

    #pragma unroll 2
    for (int r = r0; r < r1; ++r) {
        const float4* row = (const float4*)(H + (size_t)r * NE);
        float part = 0.f;
        #pragma unroll
        for (int j = 0; j < 4; ++j) {
            int c4 = tid + j * 256;                 // float4 index, < 1000
            if (c4 < NE / 4) {
                float4 v = row[c4];
                part += (v.x + v.y) + (v.z + v.w);
                cacc[j][0] += v.x; cacc[j][1] += v.y;
                cacc[j][2] += v.z; cacc[j][3] += v.w;
            }
        }
        #pragma unroll
        for (int o = 16; o > 0; o >>= 1) part += __shfl_xor_sync(~0u, part, o);
        if (lane == 0) atomicAdd(&s_row[r - r0], part);
    }
    __syncthreads();

    if (tid < r1 - r0) {
        float s = s_row[tid];
        g_degV[r0 + tid] = (s > 0.f) ? rsqrtf(s) : 1.0f;
    }

    // flush column partials
    #pragma unroll
    for (int j = 0; j < 4; ++j) {
        int c = 4 * tid + 1024 * j;
        if (c < NE) {
            atomicAdd(&g_colsum[c + 0], cacc[j][0]);
            atomicAdd(&g_colsum[c + 1], cacc[j][1]);
            atomicAdd(&g_colsum[c + 2], cacc[j][2]);
            atomicAdd(&g_colsum[c + 3], cacc[j][3]);
        }
    }
}

// fill adjacency lists
__global__ void k_fill(const int* __restrict__ vertex, const int* __restrict__ edges) {
    int i = blockIdx.x * blockDim.x + threadIdx.x;
    if (i < NNZK) {
        int v = vertex[i]; v = (v < 0) ? 0 : (v >= NV ? NV - 1 : v);
        int e = edges[i];  e = (e < 0) ? 0 : (e >= NE ? NE - 1 : e);
        int pe = atomicAdd(&g_cur_e[e], 1);
        g_vlist[g_off_e[e] + pe] = v;
        int pv = atomicAdd(&g_cur_v[v], 1);
        g_elist[g_off_v[v] + pv] = e;
    }
}

// ---------------- prep tf32-split GEMM matrix Mt[j][k] = 0.8*W[j][k]+0.2*I --
__global__ void k_prepM(const float* __restrict__ W) {
    int i = blockIdx.x * blockDim.x + threadIdx.x;
    if (i < DD * DD) {
        int j = i >> 8, k = i & 255;
        float m = 0.8f * W[i] + ((j == k) ? 0.2f : 0.f);
        unsigned hi = f2tf32(m);
        g_Mh[i] = hi;
        g_Ml[i] = f2tf32(m - __uint_as_float(hi));
    }
}

// ---------------- edge gather: Xe[e] = rsqrt(colsum)/cnt * sum X[v] ---------
__global__ void __launch_bounds__(256) k_edge_gather(const float* __restrict__ X) {
    const int e   = blockIdx.x;
    const int tid = threadIdx.x;
    const int s = g_off_e[e];
    const int t = g_off_e[e + 1];
    float acc = 0.f;
    int i = s;
    for (; i + 8 <= t; i += 8) {
        int v0 = g_vlist[i],     v1 = g_vlist[i + 1], v2 = g_vlist[i + 2], v3 = g_vlist[i + 3];
        int v4 = g_vlist[i + 4], v5 = g_vlist[i + 5], v6 = g_vlist[i + 6], v7 = g_vlist[i + 7];
        float a = X[(size_t)v0 * DD + tid];
        float b = X[(size_t)v1 * DD + tid];
        float c = X[(size_t)v2 * DD + tid];
        float d = X[(size_t)v3 * DD + tid];
        float a2 = X[(size_t)v4 * DD + tid];
        float b2 = X[(size_t)v5 * DD + tid];
        float c2 = X[(size_t)v6 * DD + tid];
        float d2 = X[(size_t)v7 * DD + tid];
        acc += ((a + b) + (c + d)) + ((a2 + b2) + (c2 + d2));
    }
    for (; i < t; ++i) acc += X[(size_t)g_vlist[i] * DD + tid];
    float cnt = fmaxf((float)(t - s), 1.0f);
    float scale = rsqrtf(g_colsum[e]) / cnt;          // degE folded in
    g_Xe[(size_t)e * DD + tid] = acc * scale;
}

// ---------------- vertex gather: Xv[v] = sum_{e ∋ v} Xe[e] ------------------
__global__ void __launch_bounds__(256) k_vert_gather() {
    int v = blockIdx.x * 8 + (threadIdx.x >> 5);
    if (v >= NV) return;
    const int lane = threadIdx.x & 31;
    const int s = g_off_v[v];
    const int t = g_off_v[v + 1];
    float4 a0 = make_float4(0.f, 0.f, 0.f, 0.f);
    float4 a1 = a0;
    int i = s;
    for (; i + 4 <= t; i += 4) {
        int e0 = g_elist[i], e1 = g_elist[i + 1], e2 = g_elist[i + 2], e3 = g_elist[i + 3];
        const float4* r0 = (const float4*)(g_Xe + (size_t)e0 * DD);
        const float4* r1 = (const float4*)(g_Xe + (size_t)e1 * DD);
        const float4* r2 = (const float4*)(g_Xe + (size_t)e2 * DD);
        const float4* r3 = (const float4*)(g_Xe + (size_t)e3 * DD);
        float4 x0 = r0[lane], y0 = r0[lane + 32];
        float4 x1 = r1[lane], y1 = r1[lane + 32];
        float4 x2 = r2[lane], y2 = r2[lane + 32];
        float4 x3 = r3[lane], y3 = r3[lane + 32];
        a0.x += (x0.x + x1.x) + (x2.x + x3.x); a0.y += (x0.y + x1.y) + (x2.y + x3.y);
        a0.z += (x0.z + x1.z) + (x2.z + x3.z); a0.w += (x0.w + x1.w) + (x2.w + x3.w);
        a1.x += (y0.x + y1.x) + (y2.x + y3.x); a1.y += (y0.y + y1.y) + (y2.y + y3.y);
        a1.z += (y0.z + y1.z) + (y2.z + y3.z); a1.w += (y0.w + y1.w) + (y2.w + y3.w);
    }
    for (; i < t; ++i) {
        const float4* r0 = (const float4*)(g_Xe + (size_t)g_elist[i] * DD);
        float4 x0 = r0[lane], y0 = r0[lane + 32];
        a0.x += x0.x; a0.y += x0.y; a0.z += x0.z; a0.w += x0.w;
        a1.x += y0.x; a1.y += y0.y; a1.z += y0.z; a1.w += y0.w;
    }
    float4* dst = (float4*)(g_Xv + (size_t)v * DD);
    dst[lane]      = a0;
    dst[lane + 32] = a1;
}

// ---------------- 3xTF32 tensor-core GEMM: out = Xi @ M ---------------------
__global__ void __launch_bounds__(256) k_gemm(const float* __restrict__ X0,
                                              float* __restrict__ out)
{
    __shared__ unsigned As_hi[16][132];
    __shared__ unsigned As_lo[16][132];
    __shared__ unsigned Bs_hi[128][20];
    __shared__ unsigned Bs_lo[128][20];

    const int tid  = threadIdx.x;
    const int lane = tid & 31;
    const int wid  = tid >> 5;
    const int gid  = lane >> 2;
    const int tig  = lane & 3;
    const int wr   = wid & 3;
    const int wc   = wid >> 2;
    const int n0   = blockIdx.x * 128;
    const int j0   = blockIdx.y * 128;

    const int lrow  = tid >> 1;
    const int lhalf = (tid & 1) * 8;

    float acc[2][8][4];
    #pragma unroll
    for (int mb = 0; mb < 2; ++mb)
        #pragma unroll
        for (int nb = 0; nb < 8; ++nb)
            #pragma unroll
            for (int c = 0; c < 4; ++c) acc[mb][nb][c] = 0.f;

    const int gRow = n0 + lrow;
    const float dv = (gRow < NV) ? g_degV[gRow] : 0.f;
    const float sc = 0.9f * dv;

    for (int k0 = 0; k0 < DD; k0 += 16) {
        float xi[8];
        if (gRow < NV) {
            size_t off = (size_t)gRow * DD + k0 + lhalf;
            float4 xa = *(const float4*)(g_Xv + off);
            float4 xb = *(const float4*)(g_Xv + off + 4);
            float4 za = *(const float4*)(X0 + off);
            float4 zb = *(const float4*)(X0 + off + 4);
            xi[0] = sc * xa.x + 0.1f * za.x; xi[1] = sc * xa.y + 0.1f * za.y;
            xi[2] = sc * xa.z + 0.1f * za.z; xi[3] = sc * xa.w + 0.1f * za.w;
            xi[4] = sc * xb.x + 0.1f * zb.x; xi[5] = sc * xb.y + 0.1f * zb.y;
            xi[6] = sc * xb.z + 0.1f * zb.z; xi[7] = sc * xb.w + 0.1f * zb.w;
        } else {
            #pragma unroll
            for (int c = 0; c < 8; ++c) xi[c] = 0.f;
        }
        #pragma unroll
        for (int c = 0; c < 8; ++c) {
            unsigned hi = f2tf32(xi[c]);
            As_hi[lhalf + c][lrow] = hi;
            As_lo[lhalf + c][lrow] = f2tf32(xi[c] - __uint_as_float(hi));
        }
        {
            size_t off = (size_t)(j0 + lrow) * DD + k0 + lhalf;
            uint4 h0 = *(const uint4*)(g_Mh + off);
            uint4 h1 = *(const uint4*)(g_Mh + off + 4);
            uint4 l0 = *(const uint4*)(g_Ml + off);
            uint4 l1 = *(const uint4*)(g_Ml + off + 4);
            *(uint4*)&Bs_hi[lrow][lhalf]     = h0;
            *(uint4*)&Bs_hi[lrow][lhalf + 4] = h1;
            *(uint4*)&Bs_lo[lrow][lhalf]     = l0;
            *(uint4*)&Bs_lo[lrow][lhalf + 4] = l1;
        }
        __syncthreads();

        #pragma unroll
        for (int kk = 0; kk < 16; kk += 8) {
            unsigned bh[8][2], bl[8][2];
            #pragma unroll
            for (int nb = 0; nb < 8; ++nb) {
                int n = wc * 64 + nb * 8 + gid;
                bh[nb][0] = Bs_hi[n][kk + tig];
                bh[nb][1] = Bs_hi[n][kk + tig + 4];
                bl[nb][0] = Bs_lo[n][kk + tig];
                bl[nb][1] = Bs_lo[n][kk + tig + 4];
            }
            #pragma unroll
            for (int mb = 0; mb < 2; ++mb) {
                int m = wr * 32 + mb * 16 + gid;
                unsigned ah[4], al[4];
                ah[0] = As_hi[kk + tig][m];     ah[1] = As_hi[kk + tig][m + 8];
                ah[2] = As_hi[kk + tig + 4][m]; ah[3] = As_hi[kk + tig + 4][m + 8];
                al[0] = As_lo[kk + tig][m];     al[1] = As_lo[kk + tig][m + 8];
                al[2] = As_lo[kk + tig + 4][m]; al[3] = As_lo[kk + tig + 4][m + 8];
                #pragma unroll
                for (int nb = 0; nb < 8; ++nb) {
                    mma_tf32(acc[mb][nb], ah, bh[nb]);
                    mma_tf32(acc[mb][nb], ah, bl[nb]);
                    mma_tf32(acc[mb][nb], al, bh[nb]);
                }
            }
        }
        __syncthreads();
    }

    #pragma unroll
    for (int mb = 0; mb < 2; ++mb) {
        int row = n0 + wr * 32 + mb * 16 + gid;
        #pragma unroll
        for (int nb = 0; nb < 8; ++nb) {
            int col = j0 + wc * 64 + nb * 8 + tig * 2;
            if (row < NV) {
                float2 v = make_float2(acc[mb][nb][0], acc[mb][nb][1]);
                *(float2*)(out + (size_t)row * DD + col) = v;
            }
            if (row + 8 < NV) {
                float2 v = make_float2(acc[mb][nb][2], acc[mb][nb][3]);
                *(float2*)(out + (size_t)(row + 8) * DD + col) = v;
            }
        }
    }
}

// ---------------- launch ------------------------------------------------------
extern "C" void kernel_launch(void* const* d_in, const int* in_sizes, int n_in,
                              void* d_out, int out_size)
{
    const float* X      = (const float*)d_in[0];
    const float* X0     = (const float*)d_in[1];
    const float* H      = (const float*)d_in[2];
    const float* W      = (const float*)d_in[3];
    const int*   vertex = (const int*)d_in[4];
    const int*   edges  = (const int*)d_in[5];
    float* out = (float*)d_out;

    k_zero_small<<<(NV + 255) / 256, 256>>>();                 // 1
    k_hist<<<(NNZK + 255) / 256, 256>>>(vertex, edges);        // 2
    k_scan_e<<<1, 1024>>>();                                   // 3
    k_deg<<<(NV + DEG_ROWS - 1) / DEG_ROWS, 256>>>(H);         // 4  <- profiled slot
    k_scan_v<<<1, 1024>>>();                                   // 5
    k_fill<<<(NNZK + 255) / 256, 256>>>(vertex, edges);        // 6
    k_prepM<<<(DD * DD + 255) / 256, 256>>>(W);                // 7
    k_edge_gather<<<NE, 256>>>(X);                             // 8
    k_vert_gather<<<(NV + 7) / 8, 256>>>();                    // 9
    k_gemm<<<dim3((NV + 127) / 128, DD / 128), 256>>>(X0, out);// 10
}

// round 8
// speedup vs baseline: 1.3804x; 1.0654x over previous
#include <cuda_runtime.h>
#include <cstdint>

#define NV   30000
#define NE   4000
#define DD   256
#define NNZK 960000

// ---------------- scratch (static device globals; aligned) ------------------
__device__ __align__(256) float g_degV[NV];
__device__ __align__(256) float g_colsum[NE];
__device__ __align__(256) float g_Xe[NE * DD];            // 4 MB
__device__ __align__(256) float g_Xv[NV * DD];            // 30 MB
__device__ __align__(256) unsigned g_Mh[DD * DD];         // tf32 hi of 0.8*W^T+0.2I
__device__ __align__(256) unsigned g_Ml[DD * DD];         // tf32 lo

// CSR scratch
__device__ __align__(256) int g_cnt_e[NE + 1];
__device__ __align__(256) int g_off_e[NE + 1];
__device__ __align__(256) int g_cur_e[NE];
__device__ __align__(256) int g_vlist[NNZK];
__device__ __align__(256) int g_cnt_v[NV + 1];
__device__ __align__(256) int g_off_v[NV + 1];
__device__ __align__(256) int g_cur_v[NV];
__device__ __align__(256) int g_elist[NNZK];

// ---------------- tf32 helpers ----------------------------------------------
__device__ __forceinline__ unsigned f2tf32(float x) {
    unsigned r; asm("cvt.rna.tf32.f32 %0, %1;" : "=r"(r) : "f"(x)); return r;
}
__device__ __forceinline__ void mma_tf32(float* d, const unsigned* a, const unsigned* b) {
    asm volatile(
        "mma.sync.aligned.m16n8k8.row.col.f32.tf32.tf32.f32 "
        "{%0,%1,%2,%3}, {%4,%5,%6,%7}, {%8,%9}, {%0,%1,%2,%3};\n"
        : "+f"(d[0]), "+f"(d[1]), "+f"(d[2]), "+f"(d[3])
        : "r"(a[0]), "r"(a[1]), "r"(a[2]), "r"(a[3]), "r"(b[0]), "r"(b[1]));
}

// ---------------- small zero-init -------------------------------------------
__global__ void k_zero_small() {
    int i = blockIdx.x * blockDim.x + threadIdx.x;
    if (i < NE) { g_colsum[i] = 0.f; g_cnt_e[i] = 0; g_cur_e[i] = 0; }
    if (i < NV) { g_cnt_v[i] = 0; g_cur_v[i] = 0; }
}

// ---------------- CSR build: histogram --------------------------------------
__global__ void k_hist(const int* __restrict__ vertex, const int* __restrict__ edges) {
    int i = blockIdx.x * blockDim.x + threadIdx.x;
    if (i < NNZK) {
        int v = vertex[i]; v = (v < 0) ? 0 : (v >= NV ? NV - 1 : v);
        int e = edges[i];  e = (e < 0) ? 0 : (e >= NE ? NE - 1 : e);
        atomicAdd(&g_cnt_e[e], 1);
        atomicAdd(&g_cnt_v[v], 1);
    }
}

// single-block exclusive scan (device-side symbol refs only)
__device__ __forceinline__ void scan_impl(const int* __restrict__ cnt,
                                          int* __restrict__ off, int n) {
    __shared__ int wsum[32];
    __shared__ int carry_s;
    int lane = threadIdx.x & 31, wid = threadIdx.x >> 5;
    if (threadIdx.x == 0) carry_s = 0;
    __syncthreads();
    for (int base = 0; base < n; base += 1024) {
        int i = base + threadIdx.x;
        int x = (i < n) ? cnt[i] : 0;
        int inc = x;
        #pragma unroll
        for (int d = 1; d < 32; d <<= 1) {
            int t = __shfl_up_sync(~0u, inc, d);
            if (lane >= d) inc += t;
        }
        if (lane == 31) wsum[wid] = inc;
        __syncthreads();
        if (wid == 0) {
            int w = wsum[lane];
            #pragma unroll
            for (int d = 1; d < 32; d <<= 1) {
                int t = __shfl_up_sync(~0u, w, d);
                if (lane >= d) w += t;
            }
            wsum[lane] = w;
        }
        __syncthreads();
        int woff = (wid > 0) ? wsum[wid - 1] : 0;
        if (i < n) off[i] = carry_s + woff + inc - x;
        __syncthreads();
        if (threadIdx.x == 1023) carry_s += wsum[31];
        __syncthreads();
    }
    if (threadIdx.x == 0) off[n] = carry_s;
}
// both scans in one launch; they run concurrently on 2 blocks
__global__ void __launch_bounds__(1024) k_scan_ev() {
    if (blockIdx.x == 0) scan_impl(g_cnt_e, g_off_e, NE);
    else                 scan_impl(g_cnt_v, g_off_v, NV);
}

// ---------------- fused H row-sum + col-sum (single 480MB pass) --------------
// 512 threads, each owns 2 float4 columns. Rows processed in explicit batches
// of 4 with ALL loads issued before any reduction -> MLP ~8/thread.
#define DEG_ROWS 32
__global__ void __launch_bounds__(512) k_deg(const float* __restrict__ H) {
    __shared__ float s_row[DEG_ROWS];
    const int tid  = threadIdx.x;
    const int lane = tid & 31;

    if (tid < DEG_ROWS) s_row[tid] = 0.f;
    __syncthreads();

    const int c0 = tid;          // always < 1000
    const int c1 = tid + 512;    // valid if < 1000
    const bool p1 = (c1 < NE / 4);

    float cacc[2][4];
    #pragma unroll
    for (int j = 0; j < 2; ++j)
        #pragma unroll
        for (int k = 0; k < 4; ++k) cacc[j][k] = 0.f;

    const int r0 = blockIdx.x * DEG_ROWS;
    const float4 z4 = make_float4(0.f, 0.f, 0.f, 0.f);

    for (int rb = 0; rb < DEG_ROWS; rb += 4) {
        // ---- batched loads: 8 float4 in flight before any use ----
        float4 v[4][2];
        #pragma unroll
        for (int i = 0; i < 4; ++i) {
            int r = r0 + rb + i;
            if (r < NV) {
                const float4* row = (const float4*)(H + (size_t)r * NE);
                v[i][0] = row[c0];
                v[i][1] = p1 ? row[c1] : z4;
            } else {
                v[i][0] = z4; v[i][1] = z4;
            }
        }
        // ---- consume ----
        #pragma unroll
        for (int i = 0; i < 4; ++i) {
            cacc[0][0] += v[i][0].x; cacc[0][1] += v[i][0].y;
            cacc[0][2] += v[i][0].z; cacc[0][3] += v[i][0].w;
            cacc[1][0] += v[i][1].x; cacc[1][1] += v[i][1].y;
            cacc[1][2] += v[i][1].z; cacc[1][3] += v[i][1].w;
            float part = ((v[i][0].x + v[i][0].y) + (v[i][0].z + v[i][0].w))
                       + ((v[i][1].x + v[i][1].y) + (v[i][1].z + v[i][1].w));
            #pragma unroll
            for (int o = 16; o > 0; o >>= 1) part += __shfl_xor_sync(~0u, part, o);
            if (lane == 0) atomicAdd(&s_row[rb + i], part);
        }
    }
    __syncthreads();

    if (tid < DEG_ROWS && r0 + tid < NV) {
        float s = s_row[tid];
        g_degV[r0 + tid] = (s > 0.f) ? rsqrtf(s) : 1.0f;
    }

    // flush column partials
    {
        int c = 4 * c0;
        atomicAdd(&g_colsum[c + 0], cacc[0][0]);
        atomicAdd(&g_colsum[c + 1], cacc[0][1]);
        atomicAdd(&g_colsum[c + 2], cacc[0][2]);
        atomicAdd(&g_colsum[c + 3], cacc[0][3]);
    }
    if (p1) {
        int c = 4 * c1;
        atomicAdd(&g_colsum[c + 0], cacc[1][0]);
        atomicAdd(&g_colsum[c + 1], cacc[1][1]);
        atomicAdd(&g_colsum[c + 2], cacc[1][2]);
        atomicAdd(&g_colsum[c + 3], cacc[1][3]);
    }
}

// fill adjacency lists
__global__ void k_fill(const int* __restrict__ vertex, const int* __restrict__ edges) {
    int i = blockIdx.x * blockDim.x + threadIdx.x;
    if (i < NNZK) {
        int v = vertex[i]; v = (v < 0) ? 0 : (v >= NV ? NV - 1 : v);
        int e = edges[i];  e = (e < 0) ? 0 : (e >= NE ? NE - 1 : e);
        int pe = atomicAdd(&g_cur_e[e], 1);
        g_vlist[g_off_e[e] + pe] = v;
        int pv = atomicAdd(&g_cur_v[v], 1);
        g_elist[g_off_v[v] + pv] = e;
    }
}

// ---------------- prep tf32-split GEMM matrix Mt[j][k] = 0.8*W[j][k]+0.2*I --
__global__ void k_prepM(const float* __restrict__ W) {
    int i = blockIdx.x * blockDim.x + threadIdx.x;
    if (i < DD * DD) {
        int j = i >> 8, k = i & 255;
        float m = 0.8f * W[i] + ((j == k) ? 0.2f : 0.f);
        unsigned hi = f2tf32(m);
        g_Mh[i] = hi;
        g_Ml[i] = f2tf32(m - __uint_as_float(hi));
    }
}

// ---------------- edge gather: Xe[e] = rsqrt(colsum)/cnt * sum X[v] ---------
__global__ void __launch_bounds__(256) k_edge_gather(const float* __restrict__ X) {
    const int e   = blockIdx.x;
    const int tid = threadIdx.x;
    const int s = g_off_e[e];
    const int t = g_off_e[e + 1];
    float acc = 0.f;
    int i = s;
    for (; i + 8 <= t; i += 8) {
        int v0 = g_vlist[i],     v1 = g_vlist[i + 1], v2 = g_vlist[i + 2], v3 = g_vlist[i + 3];
        int v4 = g_vlist[i + 4], v5 = g_vlist[i + 5], v6 = g_vlist[i + 6], v7 = g_vlist[i + 7];
        float a = X[(size_t)v0 * DD + tid];
        float b = X[(size_t)v1 * DD + tid];
        float c = X[(size_t)v2 * DD + tid];
        float d = X[(size_t)v3 * DD + tid];
        float a2 = X[(size_t)v4 * DD + tid];
        float b2 = X[(size_t)v5 * DD + tid];
        float c2 = X[(size_t)v6 * DD + tid];
        float d2 = X[(size_t)v7 * DD + tid];
        acc += ((a + b) + (c + d)) + ((a2 + b2) + (c2 + d2));
    }
    for (; i < t; ++i) acc += X[(size_t)g_vlist[i] * DD + tid];
    float cnt = fmaxf((float)(t - s), 1.0f);
    float scale = rsqrtf(g_colsum[e]) / cnt;
    g_Xe[(size_t)e * DD + tid] = acc * scale;
}

// ---------------- vertex gather: Xv[v] = sum_{e ∋ v} Xe[e] ------------------
__global__ void __launch_bounds__(256) k_vert_gather() {
    int v = blockIdx.x * 8 + (threadIdx.x >> 5);
    if (v >= NV) return;
    const int lane = threadIdx.x & 31;
    const int s = g_off_v[v];
    const int t = g_off_v[v + 1];
    float4 a0 = make_float4(0.f, 0.f, 0.f, 0.f);
    float4 a1 = a0;
    int i = s;
    for (; i + 4 <= t; i += 4) {
        int e0 = g_elist[i], e1 = g_elist[i + 1], e2 = g_elist[i + 2], e3 = g_elist[i + 3];
        const float4* r0 = (const float4*)(g_Xe + (size_t)e0 * DD);
        const float4* r1 = (const float4*)(g_Xe + (size_t)e1 * DD);
        const float4* r2 = (const float4*)(g_Xe + (size_t)e2 * DD);
        const float4* r3 = (const float4*)(g_Xe + (size_t)e3 * DD);
        float4 x0 = r0[lane], y0 = r0[lane + 32];
        float4 x1 = r1[lane], y1 = r1[lane + 32];
        float4 x2 = r2[lane], y2 = r2[lane + 32];
        float4 x3 = r3[lane], y3 = r3[lane + 32];
        a0.x += (x0.x + x1.x) + (x2.x + x3.x); a0.y += (x0.y + x1.y) + (x2.y + x3.y);
        a0.z += (x0.z + x1.z) + (x2.z + x3.z); a0.w += (x0.w + x1.w) + (x2.w + x3.w);
        a1.x += (y0.x + y1.x) + (y2.x + y3.x); a1.y += (y0.y + y1.y) + (y2.y + y3.y);
        a1.z += (y0.z + y1.z) + (y2.z + y3.z); a1.w += (y0.w + y1.w) + (y2.w + y3.w);
    }
    for (; i < t; ++i) {
        const float4* r0 = (const float4*)(g_Xe + (size_t)g_elist[i] * DD);
        float4 x0 = r0[lane], y0 = r0[lane + 32];
        a0.x += x0.x; a0.y += x0.y; a0.z += x0.z; a0.w += x0.w;
        a1.x += y0.x; a1.y += y0.y; a1.z += y0.z; a1.w += y0.w;
    }
    float4* dst = (float4*)(g_Xv + (size_t)v * DD);
    dst[lane]      = a0;
    dst[lane + 32] = a1;
}

// ---------------- 3xTF32 tensor-core GEMM: out = Xi @ M ---------------------
__global__ void __launch_bounds__(256) k_gemm(const float* __restrict__ X0,
                                              float* __restrict__ out)
{
    __shared__ unsigned As_hi[16][132];
    __shared__ unsigned As_lo[16][132];
    __shared__ unsigned Bs_hi[128][20];
    __shared__ unsigned Bs_lo[128][20];

    const int tid  = threadIdx.x;
    const int lane = tid & 31;
    const int wid  = tid >> 5;
    const int gid  = lane >> 2;
    const int tig  = lane & 3;
    const int wr   = wid & 3;
    const int wc   = wid >> 2;
    const int n0   = blockIdx.x * 128;
    const int j0   = blockIdx.y * 128;

    const int lrow  = tid >> 1;
    const int lhalf = (tid & 1) * 8;

    float acc[2][8][4];
    #pragma unroll
    for (int mb = 0; mb < 2; ++mb)
        #pragma unroll
        for (int nb = 0; nb < 8; ++nb)
            #pragma unroll
            for (int c = 0; c < 4; ++c) acc[mb][nb][c] = 0.f;

    const int gRow = n0 + lrow;
    const float dv = (gRow < NV) ? g_degV[gRow] : 0.f;
    const float sc = 0.9f * dv;

    for (int k0 = 0; k0 < DD; k0 += 16) {
        float xi[8];
        if (gRow < NV) {
            size_t off = (size_t)gRow * DD + k0 + lhalf;
            float4 xa = *(const float4*)(g_Xv + off);
            float4 xb = *(const float4*)(g_Xv + off + 4);
            float4 za = *(const float4*)(X0 + off);
            float4 zb = *(const float4*)(X0 + off + 4);
            xi[0] = sc * xa.x + 0.1f * za.x; xi[1] = sc * xa.y + 0.1f * za.y;
            xi[2] = sc * xa.z + 0.1f * za.z; xi[3] = sc * xa.w + 0.1f * za.w;
            xi[4] = sc * xb.x + 0.1f * zb.x; xi[5] = sc * xb.y + 0.1f * zb.y;
            xi[6] = sc * xb.z + 0.1f * zb.z; xi[7] = sc * xb.w + 0.1f * zb.w;
        } else {
            #pragma unroll
            for (int c = 0; c < 8; ++c) xi[c] = 0.f;
        }
        #pragma unroll
        for (int c = 0; c < 8; ++c) {
            unsigned hi = f2tf32(xi[c]);
            As_hi[lhalf + c][lrow] = hi;
            As_lo[lhalf + c][lrow] = f2tf32(xi[c] - __uint_as_float(hi));
        }
        {
            size_t off = (size_t)(j0 + lrow) * DD + k0 + lhalf;
            uint4 h0 = *(const uint4*)(g_Mh + off);
            uint4 h1 = *(const uint4*)(g_Mh + off + 4);
            uint4 l0 = *(const uint4*)(g_Ml + off);
            uint4 l1 = *(const uint4*)(g_Ml + off + 4);
            *(uint4*)&Bs_hi[lrow][lhalf]     = h0;
            *(uint4*)&Bs_hi[lrow][lhalf + 4] = h1;
            *(uint4*)&Bs_lo[lrow][lhalf]     = l0;
            *(uint4*)&Bs_lo[lrow][lhalf + 4] = l1;
        }
        __syncthreads();

        #pragma unroll
        for (int kk = 0; kk < 16; kk += 8) {
            unsigned bh[8][2], bl[8][2];
            #pragma unroll
            for (int nb = 0; nb < 8; ++nb) {
                int n = wc * 64 + nb * 8 + gid;
                bh[nb][0] = Bs_hi[n][kk + tig];
                bh[nb][1] = Bs_hi[n][kk + tig + 4];
                bl[nb][0] = Bs_lo[n][kk + tig];
                bl[nb][1] = Bs_lo[n][kk + tig + 4];
            }
            #pragma unroll
            for (int mb = 0; mb < 2; ++mb) {
                int m = wr * 32 + mb * 16 + gid;
                unsigned ah[4], al[4];
                ah[0] = As_hi[kk + tig][m];     ah[1] = As_hi[kk + tig][m + 8];
                ah[2] = As_hi[kk + tig + 4][m]; ah[3] = As_hi[kk + tig + 4][m + 8];
                al[0] = As_lo[kk + tig][m];     al[1] = As_lo[kk + tig][m + 8];
                al[2] = As_lo[kk + tig + 4][m]; al[3] = As_lo[kk + tig + 4][m + 8];
                #pragma unroll
                for (int nb = 0; nb < 8; ++nb) {
                    mma_tf32(acc[mb][nb], ah, bh[nb]);
                    mma_tf32(acc[mb][nb], ah, bl[nb]);
                    mma_tf32(acc[mb][nb], al, bh[nb]);
                }
            }
        }
        __syncthreads();
    }

    #pragma unroll
    for (int mb = 0; mb < 2; ++mb) {
        int row = n0 + wr * 32 + mb * 16 + gid;
        #pragma unroll
        for (int nb = 0; nb < 8; ++nb) {
            int col = j0 + wc * 64 + nb * 8 + tig * 2;
            if (row < NV) {
                float2 v = make_float2(acc[mb][nb][0], acc[mb][nb][1]);
                *(float2*)(out + (size_t)row * DD + col) = v;
            }
            if (row + 8 < NV) {
                float2 v = make_float2(acc[mb][nb][2], acc[mb][nb][3]);
                *(float2*)(out + (size_t)(row + 8) * DD + col) = v;
            }
        }
    }
}

// ---------------- launch ------------------------------------------------------
extern "C" void kernel_launch(void* const* d_in, const int* in_sizes, int n_in,
                              void* d_out, int out_size)
{
    const float* X      = (const float*)d_in[0];
    const float* X0     = (const float*)d_in[1];
    const float* H      = (const float*)d_in[2];
    const float* W      = (const float*)d_in[3];
    const int*   vertex = (const int*)d_in[4];
    const int*   edges  = (const int*)d_in[5];
    float* out = (float*)d_out;

    k_zero_small<<<(NV + 255) / 256, 256>>>();                 // 1
    k_hist<<<(NNZK + 255) / 256, 256>>>(vertex, edges);        // 2
    k_scan_ev<<<2, 1024>>>();                                  // 3
    k_deg<<<(NV + DEG_ROWS - 1) / DEG_ROWS, 512>>>(H);         // 4  <- profiled slot
    k_fill<<<(NNZK + 255) / 256, 256>>>(vertex, edges);        // 5
    k_prepM<<<(DD * DD + 255) / 256, 256>>>(W);                // 6
    k_edge_gather<<<NE, 256>>>(X);                             // 7
    k_vert_gather<<<(NV + 7) / 8, 256>>>();                    // 8
    k_gemm<<<dim3((NV + 127) / 128, DD / 128), 256>>>(X0, out);// 9
}

// round 10
// speedup vs baseline: 1.3945x; 1.0102x over previous
#include <cuda_runtime.h>
#include <cstdint>

#define NV   30000
#define NE   4000
#define DD   256
#define NNZK 960000

// ---------------- scratch (static device globals; zero-initialized at load) --
// INVARIANT: g_cnt_*, g_cur_*, g_colsum are zero at entry of every call;
// k_zero_tail (last launch) restores this for the next call/replay.
__device__ __align__(256) float g_degV[NV];
__device__ __align__(256) float g_colsum[NE];
__device__ __align__(256) float g_Xe[NE * DD];            // 4 MB (raw edge sums)
__device__ __align__(256) float g_Xv[NV * DD];            // 30 MB
__device__ __align__(256) unsigned g_Mh[DD * DD];         // tf32 hi of 0.8*W^T+0.2I
__device__ __align__(256) unsigned g_Ml[DD * DD];         // tf32 lo

// CSR scratch
__device__ __align__(256) int g_cnt_e[NE + 1];
__device__ __align__(256) int g_off_e[NE + 1];
__device__ __align__(256) int g_cur_e[NE];
__device__ __align__(256) int g_vlist[NNZK];
__device__ __align__(256) int g_cnt_v[NV + 1];
__device__ __align__(256) int g_off_v[NV + 1];
__device__ __align__(256) int g_cur_v[NV];
__device__ __align__(256) int g_elist[NNZK];

// ---------------- tf32 helpers ----------------------------------------------
__device__ __forceinline__ unsigned f2tf32(float x) {
    unsigned r; asm("cvt.rna.tf32.f32 %0, %1;" : "=r"(r) : "f"(x)); return r;
}
__device__ __forceinline__ void mma_tf32(float* d, const unsigned* a, const unsigned* b) {
    asm volatile(
        "mma.sync.aligned.m16n8k8.row.col.f32.tf32.tf32.f32 "
        "{%0,%1,%2,%3}, {%4,%5,%6,%7}, {%8,%9}, {%0,%1,%2,%3};\n"
        : "+f"(d[0]), "+f"(d[1]), "+f"(d[2]), "+f"(d[3])
        : "r"(a[0]), "r"(a[1]), "r"(a[2]), "r"(a[3]), "r"(b[0]), "r"(b[1]));
}

// ---------------- CSR build: histogram (cnt_* are pre-zeroed) ----------------
__global__ void k_hist(const int* __restrict__ vertex, const int* __restrict__ edges) {
    int i = blockIdx.x * blockDim.x + threadIdx.x;
    if (i < NNZK) {
        int v = vertex[i]; v = (v < 0) ? 0 : (v >= NV ? NV - 1 : v);
        int e = edges[i];  e = (e < 0) ? 0 : (e >= NE ? NE - 1 : e);
        atomicAdd(&g_cnt_e[e], 1);
        atomicAdd(&g_cnt_v[v], 1);
    }
}

// single-block exclusive scan (device-side symbol refs only)
__device__ __forceinline__ void scan_impl(const int* __restrict__ cnt,
                                          int* __restrict__ off, int n) {
    __shared__ int wsum[32];
    __shared__ int carry_s;
    int lane = threadIdx.x & 31, wid = threadIdx.x >> 5;
    if (threadIdx.x == 0) carry_s = 0;
    __syncthreads();
    for (int base = 0; base < n; base += 1024) {
        int i = base + threadIdx.x;
        int x = (i < n) ? cnt[i] : 0;
        int inc = x;
        #pragma unroll
        for (int d = 1; d < 32; d <<= 1) {
            int t = __shfl_up_sync(~0u, inc, d);
            if (lane >= d) inc += t;
        }
        if (lane == 31) wsum[wid] = inc;
        __syncthreads();
        if (wid == 0) {
            int w = wsum[lane];
            #pragma unroll
            for (int d = 1; d < 32; d <<= 1) {
                int t = __shfl_up_sync(~0u, w, d);
                if (lane >= d) w += t;
            }
            wsum[lane] = w;
        }
        __syncthreads();
        int woff = (wid > 0) ? wsum[wid - 1] : 0;
        if (i < n) off[i] = carry_s + woff + inc - x;
        __syncthreads();
        if (threadIdx.x == 1023) carry_s += wsum[31];
        __syncthreads();
    }
    if (threadIdx.x == 0) off[n] = carry_s;
}
__global__ void __launch_bounds__(1024) k_scan_ev() {
    if (blockIdx.x == 0) scan_impl(g_cnt_e, g_off_e, NE);
    else                 scan_impl(g_cnt_v, g_off_v, NV);
}

// fill adjacency lists (cur_* pre-zeroed)
__global__ void k_fill(const int* __restrict__ vertex, const int* __restrict__ edges) {
    int i = blockIdx.x * blockDim.x + threadIdx.x;
    if (i < NNZK) {
        int v = vertex[i]; v = (v < 0) ? 0 : (v >= NV ? NV - 1 : v);
        int e = edges[i];  e = (e < 0) ? 0 : (e >= NE ? NE - 1 : e);
        int pe = atomicAdd(&g_cur_e[e], 1);
        g_vlist[g_off_e[e] + pe] = v;
        int pv = atomicAdd(&g_cur_v[v], 1);
        g_elist[g_off_v[v] + pv] = e;
    }
}

// ---------------- edge gather (RAW sums, scale deferred): Xe[e] = sum X[v] --
// smem-staged indices; 8 gathers in flight per thread.
__global__ void __launch_bounds__(256) k_edge_gather(const float* __restrict__ X) {
    __shared__ int sIdx[256];
    const int e   = blockIdx.x;
    const int tid = threadIdx.x;
    const int s = g_off_e[e];
    const int t = g_off_e[e + 1];
    float acc = 0.f;
    for (int ib = s; ib < t; ib += 256) {
        int n = t - ib; if (n > 256) n = 256;
        if (tid < n) sIdx[tid] = g_vlist[ib + tid];
        __syncthreads();
        int j = 0;
        for (; j + 8 <= n; j += 8) {
            int v0 = sIdx[j],     v1 = sIdx[j + 1], v2 = sIdx[j + 2], v3 = sIdx[j + 3];
            int v4 = sIdx[j + 4], v5 = sIdx[j + 5], v6 = sIdx[j + 6], v7 = sIdx[j + 7];
            float a  = X[(size_t)v0 * DD + tid];
            float b  = X[(size_t)v1 * DD + tid];
            float c  = X[(size_t)v2 * DD + tid];
            float d  = X[(size_t)v3 * DD + tid];
            float a2 = X[(size_t)v4 * DD + tid];
            float b2 = X[(size_t)v5 * DD + tid];
            float c2 = X[(size_t)v6 * DD + tid];
            float d2 = X[(size_t)v7 * DD + tid];
            acc += ((a + b) + (c + d)) + ((a2 + b2) + (c2 + d2));
        }
        for (; j < n; ++j) acc += X[(size_t)sIdx[j] * DD + tid];
        __syncthreads();
    }
    g_Xe[(size_t)e * DD + tid] = acc;
}

// ---------------- fused H row-sum + col-sum (single 480MB pass) --------------
#define DEG_ROWS 32
__global__ void __launch_bounds__(512) k_deg(const float* __restrict__ H) {
    __shared__ float s_row[DEG_ROWS];
    const int tid  = threadIdx.x;
    const int lane = tid & 31;

    if (tid < DEG_ROWS) s_row[tid] = 0.f;
    __syncthreads();

    const int c0 = tid;
    const int c1 = tid + 512;
    const bool p1 = (c1 < NE / 4);

    float cacc[2][4];
    #pragma unroll
    for (int j = 0; j < 2; ++j)
        #pragma unroll
        for (int k = 0; k < 4; ++k) cacc[j][k] = 0.f;

    const int r0 = blockIdx.x * DEG_ROWS;
    const float4 z4 = make_float4(0.f, 0.f, 0.f, 0.f);

    for (int rb = 0; rb < DEG_ROWS; rb += 4) {
        float4 v[4][2];
        #pragma unroll
        for (int i = 0; i < 4; ++i) {
            int r = r0 + rb + i;
            if (r < NV) {
                const float4* row = (const float4*)(H + (size_t)r * NE);
                v[i][0] = row[c0];
                v[i][1] = p1 ? row[c1] : z4;
            } else {
                v[i][0] = z4; v[i][1] = z4;
            }
        }
        #pragma unroll
        for (int i = 0; i < 4; ++i) {
            cacc[0][0] += v[i][0].x; cacc[0][1] += v[i][0].y;
            cacc[0][2] += v[i][0].z; cacc[0][3] += v[i][0].w;
            cacc[1][0] += v[i][1].x; cacc[1][1] += v[i][1].y;
            cacc[1][2] += v[i][1].z; cacc[1][3] += v[i][1].w;
            float part = ((v[i][0].x + v[i][0].y) + (v[i][0].z + v[i][0].w))
                       + ((v[i][1].x + v[i][1].y) + (v[i][1].z + v[i][1].w));
            #pragma unroll
            for (int o = 16; o > 0; o >>= 1) part += __shfl_xor_sync(~0u, part, o);
            if (lane == 0) atomicAdd(&s_row[rb + i], part);
        }
    }
    __syncthreads();

    if (tid < DEG_ROWS && r0 + tid < NV) {
        float s = s_row[tid];
        g_degV[r0 + tid] = (s > 0.f) ? rsqrtf(s) : 1.0f;
    }

    {
        int c = 4 * c0;
        atomicAdd(&g_colsum[c + 0], cacc[0][0]);
        atomicAdd(&g_colsum[c + 1], cacc[0][1]);
        atomicAdd(&g_colsum[c + 2], cacc[0][2]);
        atomicAdd(&g_colsum[c + 3], cacc[0][3]);
    }
    if (p1) {
        int c = 4 * c1;
        atomicAdd(&g_colsum[c + 0], cacc[1][0]);
        atomicAdd(&g_colsum[c + 1], cacc[1][1]);
        atomicAdd(&g_colsum[c + 2], cacc[1][2]);
        atomicAdd(&g_colsum[c + 3], cacc[1][3]);
    }
}

// ---------------- vertex gather: Xv[v] = sum_e scale[e]*Xe[e] ----------------
// warp per vertex; indices+scales fetched lane-strided then shuffle-broadcast.
__global__ void __launch_bounds__(256) k_vert_gather() {
    int v = blockIdx.x * 8 + (threadIdx.x >> 5);
    if (v >= NV) return;
    const int lane = threadIdx.x & 31;
    const int s = g_off_v[v];
    const int t = g_off_v[v + 1];
    float4 a0 = make_float4(0.f, 0.f, 0.f, 0.f);
    float4 a1 = a0;

    for (int ib = s; ib < t; ib += 32) {
        int n = t - ib; if (n > 32) n = 32;
        int   myE  = 0;
        float mySc = 0.f;
        if (lane < n) {
            myE = g_elist[ib + lane];
            int cs = g_off_e[myE], ce = g_off_e[myE + 1];
            float cnt = fmaxf((float)(ce - cs), 1.0f);
            mySc = rsqrtf(g_colsum[myE]) / cnt;      // degE/cnt folded per edge
        }
        int j = 0;
        for (; j + 4 <= n; j += 4) {
            int   e0 = __shfl_sync(~0u, myE,  j);
            int   e1 = __shfl_sync(~0u, myE,  j + 1);
            int   e2 = __shfl_sync(~0u, myE,  j + 2);
            int   e3 = __shfl_sync(~0u, myE,  j + 3);
            float s0 = __shfl_sync(~0u, mySc, j);
            float s1 = __shfl_sync(~0u, mySc, j + 1);
            float s2 = __shfl_sync(~0u, mySc, j + 2);
            float s3 = __shfl_sync(~0u, mySc, j + 3);
            const float4* r0 = (const float4*)(g_Xe + (size_t)e0 * DD);
            const float4* r1 = (const float4*)(g_Xe + (size_t)e1 * DD);
            const float4* r2 = (const float4*)(g_Xe + (size_t)e2 * DD);
            const float4* r3 = (const float4*)(g_Xe + (size_t)e3 * DD);
            float4 x0 = r0[lane], y0 = r0[lane + 32];
            float4 x1 = r1[lane], y1 = r1[lane + 32];
            float4 x2 = r2[lane], y2 = r2[lane + 32];
            float4 x3 = r3[lane], y3 = r3[lane + 32];
            a0.x += s0*x0.x + s1*x1.x + s2*x2.x + s3*x3.x;
            a0.y += s0*x0.y + s1*x1.y + s2*x2.y + s3*x3.y;
            a0.z += s0*x0.z + s1*x1.z + s2*x2.z + s3*x3.z;
            a0.w += s0*x0.w + s1*x1.w + s2*x2.w + s3*x3.w;
            a1.x += s0*y0.x + s1*y1.x + s2*y2.x + s3*y3.x;
            a1.y += s0*y0.y + s1*y1.y + s2*y2.y + s3*y3.y;
            a1.z += s0*y0.z + s1*y1.z + s2*y2.z + s3*y3.z;
            a1.w += s0*y0.w + s1*y1.w + s2*y2.w + s3*y3.w;
        }
        for (; j < n; ++j) {
            int   e0 = __shfl_sync(~0u, myE,  j);
            float s0 = __shfl_sync(~0u, mySc, j);
            const float4* r0 = (const float4*)(g_Xe + (size_t)e0 * DD);
            float4 x0 = r0[lane], y0 = r0[lane + 32];
            a0.x += s0*x0.x; a0.y += s0*x0.y; a0.z += s0*x0.z; a0.w += s0*x0.w;
            a1.x += s0*y0.x; a1.y += s0*y0.y; a1.z += s0*y0.z; a1.w += s0*y0.w;
        }
    }
    float4* dst = (float4*)(g_Xv + (size_t)v * DD);
    dst[lane]      = a0;
    dst[lane + 32] = a1;
}

// ---------------- prep tf32-split GEMM matrix Mt[j][k] = 0.8*W[j][k]+0.2*I --
__global__ void k_prepM(const float* __restrict__ W) {
    int i = blockIdx.x * blockDim.x + threadIdx.x;
    if (i < DD * DD) {
        int j = i >> 8, k = i & 255;
        float m = 0.8f * W[i] + ((j == k) ? 0.2f : 0.f);
        unsigned hi = f2tf32(m);
        g_Mh[i] = hi;
        g_Ml[i] = f2tf32(m - __uint_as_float(hi));
    }
}

// ---------------- 3xTF32 tensor-core GEMM: out = Xi @ M ---------------------
__global__ void __launch_bounds__(256) k_gemm(const float* __restrict__ X0,
                                              float* __restrict__ out)
{
    __shared__ unsigned As_hi[16][132];
    __shared__ unsigned As_lo[16][132];
    __shared__ unsigned Bs_hi[128][20];
    __shared__ unsigned Bs_lo[128][20];

    const int tid  = threadIdx.x;
    const int lane = tid & 31;
    const int wid  = tid >> 5;
    const int gid  = lane >> 2;
    const int tig  = lane & 3;
    const int wr   = wid & 3;
    const int wc   = wid >> 2;
    const int n0   = blockIdx.x * 128;
    const int j0   = blockIdx.y * 128;

    const int lrow  = tid >> 1;
    const int lhalf = (tid & 1) * 8;

    float acc[2][8][4];
    #pragma unroll
    for (int mb = 0; mb < 2; ++mb)
        #pragma unroll
        for (int nb = 0; nb < 8; ++nb)
            #pragma unroll
            for (int c = 0; c < 4; ++c) acc[mb][nb][c] = 0.f;

    const int gRow = n0 + lrow;
    const float dv = (gRow < NV) ? g_degV[gRow] : 0.f;
    const float sc = 0.9f * dv;

    for (int k0 = 0; k0 < DD; k0 += 16) {
        float xi[8];
        if (gRow < NV) {
            size_t off = (size_t)gRow * DD + k0 + lhalf;
            float4 xa = *(const float4*)(g_Xv + off);
            float4 xb = *(const float4*)(g_Xv + off + 4);
            float4 za = *(const float4*)(X0 + off);
            float4 zb = *(const float4*)(X0 + off + 4);
            xi[0] = sc * xa.x + 0.1f * za.x; xi[1] = sc * xa.y + 0.1f * za.y;
            xi[2] = sc * xa.z + 0.1f * za.z; xi[3] = sc * xa.w + 0.1f * za.w;
            xi[4] = sc * xb.x + 0.1f * zb.x; xi[5] = sc * xb.y + 0.1f * zb.y;
            xi[6] = sc * xb.z + 0.1f * zb.z; xi[7] = sc * xb.w + 0.1f * zb.w;
        } else {
            #pragma unroll
            for (int c = 0; c < 8; ++c) xi[c] = 0.f;
        }
        #pragma unroll
        for (int c = 0; c < 8; ++c) {
            unsigned hi = f2tf32(xi[c]);
            As_hi[lhalf + c][lrow] = hi;
            As_lo[lhalf + c][lrow] = f2tf32(xi[c] - __uint_as_float(hi));
        }
        {
            size_t off = (size_t)(j0 + lrow) * DD + k0 + lhalf;
            uint4 h0 = *(const uint4*)(g_Mh + off);
            uint4 h1 = *(const uint4*)(g_Mh + off + 4);
            uint4 l0 = *(const uint4*)(g_Ml + off);
            uint4 l1 = *(const uint4*)(g_Ml + off + 4);
            *(uint4*)&Bs_hi[lrow][lhalf]     = h0;
            *(uint4*)&Bs_hi[lrow][lhalf + 4] = h1;
            *(uint4*)&Bs_lo[lrow][lhalf]     = l0;
            *(uint4*)&Bs_lo[lrow][lhalf + 4] = l1;
        }
        __syncthreads();

        #pragma unroll
        for (int kk = 0; kk < 16; kk += 8) {
            unsigned bh[8][2], bl[8][2];
            #pragma unroll
            for (int nb = 0; nb < 8; ++nb) {
                int n = wc * 64 + nb * 8 + gid;
                bh[nb][0] = Bs_hi[n][kk + tig];
                bh[nb][1] = Bs_hi[n][kk + tig + 4];
                bl[nb][0] = Bs_lo[n][kk + tig];
                bl[nb][1] = Bs_lo[n][kk + tig + 4];
            }
            #pragma unroll
            for (int mb = 0; mb < 2; ++mb) {
                int m = wr * 32 + mb * 16 + gid;
                unsigned ah[4], al[4];
                ah[0] = As_hi[kk + tig][m];     ah[1] = As_hi[kk + tig][m + 8];
                ah[2] = As_hi[kk + tig + 4][m]; ah[3] = As_hi[kk + tig + 4][m + 8];
                al[0] = As_lo[kk + tig][m];     al[1] = As_lo[kk + tig][m + 8];
                al[2] = As_lo[kk + tig + 4][m]; al[3] = As_lo[kk + tig + 4][m + 8];
                #pragma unroll
                for (int nb = 0; nb < 8; ++nb) {
                    mma_tf32(acc[mb][nb], ah, bh[nb]);
                    mma_tf32(acc[mb][nb], ah, bl[nb]);
                    mma_tf32(acc[mb][nb], al, bh[nb]);
                }
            }
        }
        __syncthreads();
    }

    #pragma unroll
    for (int mb = 0; mb < 2; ++mb) {
        int row = n0 + wr * 32 + mb * 16 + gid;
        #pragma unroll
        for (int nb = 0; nb < 8; ++nb) {
            int col = j0 + wc * 64 + nb * 8 + tig * 2;
            if (row < NV) {
                float2 v = make_float2(acc[mb][nb][0], acc[mb][nb][1]);
                *(float2*)(out + (size_t)row * DD + col) = v;
            }
            if (row + 8 < NV) {
                float2 v = make_float2(acc[mb][nb][2], acc[mb][nb][3]);
                *(float2*)(out + (size_t)(row + 8) * DD + col) = v;
            }
        }
    }
}

// ---------------- tail zero: restore zero-invariant for next call ------------
__global__ void k_zero_tail() {
    int i = blockIdx.x * blockDim.x + threadIdx.x;
    if (i < NE) { g_colsum[i] = 0.f; g_cnt_e[i] = 0; g_cur_e[i] = 0; }
    if (i < NV) { g_cnt_v[i] = 0; g_cur_v[i] = 0; }
}

// ---------------- launch ------------------------------------------------------
extern "C" void kernel_launch(void* const* d_in, const int* in_sizes, int n_in,
                              void* d_out, int out_size)
{
    const float* X      = (const float*)d_in[0];
    const float* X0     = (const float*)d_in[1];
    const float* H      = (const float*)d_in[2];
    const float* W      = (const float*)d_in[3];
    const int*   vertex = (const int*)d_in[4];
    const int*   edges  = (const int*)d_in[5];
    float* out = (float*)d_out;

    k_hist<<<(NNZK + 255) / 256, 256>>>(vertex, edges);        // 1
    k_scan_ev<<<2, 1024>>>();                                  // 2
    k_fill<<<(NNZK + 255) / 256, 256>>>(vertex, edges);        // 3
    k_edge_gather<<<NE, 256>>>(X);                             // 4  <- profiled slot
    k_deg<<<(NV + DEG_ROWS - 1) / DEG_ROWS, 512>>>(H);         // 5
    k_vert_gather<<<(NV + 7) / 8, 256>>>();                    // 6
    k_prepM<<<(DD * DD + 255) / 256, 256>>>(W);                // 7
    k_gemm<<<dim3((NV + 127) / 128, DD / 128), 256>>>(X0, out);// 8
    k_zero_tail<<<(NV + 255) / 256, 256>>>();                  // 9
}